// round 1
// baseline (speedup 1.0000x reference)
#include <cuda_runtime.h>
#include <math.h>

#define BB 2
#define SS 4096
#define DM 512
#define HH 8
#define DKH 64
#define NROW (BB*SS)   // 8192

// Scratch (allocation-free: __device__ globals)
__device__ float g_q[NROW * DM];
__device__ float g_k[NROW * DM];
__device__ float g_v[NROW * DM];
__device__ float g_o[NROW * DM];
__device__ float g_m[BB * HH * SS];
__device__ float g_l[BB * HH * SS];

// ---------------------------------------------------------------------------
// SGEMM: C[M,N] = A[M,K] @ W[N,K]^T + bias[N]   (torch Linear convention)
// 64x64 tile, BK=16, 256 threads, 4x4 register microtile.
// ---------------------------------------------------------------------------
__global__ __launch_bounds__(256) void sgemm_bias(
    const float* __restrict__ A, const float* __restrict__ W,
    const float* __restrict__ bias, float* __restrict__ C,
    int M, int N, int K)
{
    __shared__ float As[16][68];   // [k][m], padded
    __shared__ float Ws[16][68];   // [k][n]

    const int tid = threadIdx.x;
    const int tx = tid & 15, ty = tid >> 4;
    const int ty4 = ty * 4, tx4 = tx * 4;
    const int rowBase = blockIdx.y * 64;
    const int colBase = blockIdx.x * 64;

    const int lr = tid >> 2;          // 0..63
    const int lc = (tid & 3) * 4;     // 0,4,8,12

    float acc[4][4] = {};

    for (int k0 = 0; k0 < K; k0 += 16) {
        float4 av = *(const float4*)(A + (size_t)(rowBase + lr) * K + k0 + lc);
        float4 wv = *(const float4*)(W + (size_t)(colBase + lr) * K + k0 + lc);
        __syncthreads();
        As[lc + 0][lr] = av.x; As[lc + 1][lr] = av.y;
        As[lc + 2][lr] = av.z; As[lc + 3][lr] = av.w;
        Ws[lc + 0][lr] = wv.x; Ws[lc + 1][lr] = wv.y;
        Ws[lc + 2][lr] = wv.z; Ws[lc + 3][lr] = wv.w;
        __syncthreads();
        #pragma unroll
        for (int kk = 0; kk < 16; kk++) {
            float4 a = *(const float4*)&As[kk][ty4];
            float4 b = *(const float4*)&Ws[kk][tx4];
            acc[0][0] += a.x * b.x; acc[0][1] += a.x * b.y; acc[0][2] += a.x * b.z; acc[0][3] += a.x * b.w;
            acc[1][0] += a.y * b.x; acc[1][1] += a.y * b.y; acc[1][2] += a.y * b.z; acc[1][3] += a.y * b.w;
            acc[2][0] += a.z * b.x; acc[2][1] += a.z * b.y; acc[2][2] += a.z * b.z; acc[2][3] += a.z * b.w;
            acc[3][0] += a.w * b.x; acc[3][1] += a.w * b.y; acc[3][2] += a.w * b.z; acc[3][3] += a.w * b.w;
        }
    }

    float4 bv4 = *(const float4*)(bias + colBase + tx4);
    #pragma unroll
    for (int i = 0; i < 4; i++) {
        float4 cv = make_float4(acc[i][0] + bv4.x, acc[i][1] + bv4.y,
                                acc[i][2] + bv4.z, acc[i][3] + bv4.w);
        *(float4*)&C[(size_t)(rowBase + ty4 + i) * N + colBase + tx4] = cv;
    }
}

// ---------------------------------------------------------------------------
// s[4][4] += Qrows(ty4..) . Krows(tx4..) over dk=64, tiles stored [64][68]
// ---------------------------------------------------------------------------
__device__ __forceinline__ void dot64(const float* __restrict__ Qs,
                                      const float* __restrict__ Ks,
                                      int ty4, int tx4, float s[4][4])
{
    #pragma unroll 4
    for (int d = 0; d < 64; d += 4) {
        float4 qf[4], kf[4];
        #pragma unroll
        for (int i = 0; i < 4; i++) qf[i] = *(const float4*)&Qs[(ty4 + i) * 68 + d];
        #pragma unroll
        for (int j = 0; j < 4; j++) kf[j] = *(const float4*)&Ks[(tx4 + j) * 68 + d];
        #pragma unroll
        for (int i = 0; i < 4; i++)
            #pragma unroll
            for (int j = 0; j < 4; j++)
                s[i][j] += qf[i].x * kf[j].x + qf[i].y * kf[j].y
                         + qf[i].z * kf[j].z + qf[i].w * kf[j].w;
    }
}

// ---------------------------------------------------------------------------
// Flash attention (causal), fp32. Per block: one (b,h) and one 64-query tile.
// Also stores final per-row softmax (m, l) for optional attn writeback.
// ---------------------------------------------------------------------------
__global__ __launch_bounds__(256) void flash_attn(
    const float* __restrict__ gq, const float* __restrict__ gk,
    const float* __restrict__ gv, float* __restrict__ go,
    float* __restrict__ gm, float* __restrict__ gl)
{
    extern __shared__ float sm[];
    float* Qs = sm;                 // 64*68
    float* Ks = sm + 64 * 68;
    float* Vs = sm + 2 * 64 * 68;
    float* Ps = sm + 3 * 64 * 68;

    const int tid = threadIdx.x;
    const int tx = tid & 15, ty = tid >> 4;
    const int ty4 = ty * 4, tx4 = tx * 4;
    const int qt = 63 - blockIdx.x;       // heavy tiles scheduled first
    const int bh = blockIdx.y;
    const int b = bh >> 3, h = bh & 7;
    const int qbase = qt * 64;
    const size_t base = (size_t)b * SS * DM + h * DKH;
    const float scale = 0.125f;           // 1/sqrt(64)

    for (int f = tid; f < 1024; f += 256) {
        int r = f >> 4, c = (f & 15) << 2;
        *(float4*)&Qs[r * 68 + c] =
            *(const float4*)(gq + base + (size_t)(qbase + r) * DM + c);
    }

    float m[4], l[4], o[4][4];
    #pragma unroll
    for (int i = 0; i < 4; i++) {
        m[i] = -INFINITY; l[i] = 0.f;
        #pragma unroll
        for (int j = 0; j < 4; j++) o[i][j] = 0.f;
    }

    for (int kt = 0; kt <= qt; kt++) {
        const int kbase = kt * 64;
        __syncthreads();
        for (int f = tid; f < 1024; f += 256) {
            int r = f >> 4, c = (f & 15) << 2;
            size_t g = base + (size_t)(kbase + r) * DM + c;
            *(float4*)&Ks[r * 68 + c] = *(const float4*)(gk + g);
            *(float4*)&Vs[r * 68 + c] = *(const float4*)(gv + g);
        }
        __syncthreads();

        float s[4][4] = {};
        dot64(Qs, Ks, ty4, tx4, s);

        const bool diag = (kt == qt);
        #pragma unroll
        for (int i = 0; i < 4; i++)
            #pragma unroll
            for (int j = 0; j < 4; j++) {
                float v = s[i][j] * scale;
                if (diag && (tx4 + j) > (ty4 + i)) v = -INFINITY;
                s[i][j] = v;
            }

        #pragma unroll
        for (int i = 0; i < 4; i++) {
            float mt = fmaxf(fmaxf(s[i][0], s[i][1]), fmaxf(s[i][2], s[i][3]));
            mt = fmaxf(mt, __shfl_xor_sync(0xffffffffu, mt, 1, 16));
            mt = fmaxf(mt, __shfl_xor_sync(0xffffffffu, mt, 2, 16));
            mt = fmaxf(mt, __shfl_xor_sync(0xffffffffu, mt, 4, 16));
            mt = fmaxf(mt, __shfl_xor_sync(0xffffffffu, mt, 8, 16));
            float mn = fmaxf(m[i], mt);
            float alpha = __expf(m[i] - mn);
            m[i] = mn;
            l[i] *= alpha;
            #pragma unroll
            for (int j = 0; j < 4; j++) o[i][j] *= alpha;
            float rs = 0.f;
            #pragma unroll
            for (int j = 0; j < 4; j++) {
                float p = __expf(s[i][j] - mn);
                s[i][j] = p; rs += p;
            }
            rs += __shfl_xor_sync(0xffffffffu, rs, 1, 16);
            rs += __shfl_xor_sync(0xffffffffu, rs, 2, 16);
            rs += __shfl_xor_sync(0xffffffffu, rs, 4, 16);
            rs += __shfl_xor_sync(0xffffffffu, rs, 8, 16);
            l[i] += rs;
        }

        #pragma unroll
        for (int i = 0; i < 4; i++)
            *(float4*)&Ps[(ty4 + i) * 68 + tx4] =
                make_float4(s[i][0], s[i][1], s[i][2], s[i][3]);
        __syncthreads();

        #pragma unroll 8
        for (int k = 0; k < 64; k++) {
            float4 vv = *(const float4*)&Vs[k * 68 + tx4];
            #pragma unroll
            for (int i = 0; i < 4; i++) {
                float p = Ps[(ty4 + i) * 68 + k];
                o[i][0] += p * vv.x; o[i][1] += p * vv.y;
                o[i][2] += p * vv.z; o[i][3] += p * vv.w;
            }
        }
    }

    #pragma unroll
    for (int i = 0; i < 4; i++) {
        float inv = 1.f / l[i];
        size_t g = base + (size_t)(qbase + ty4 + i) * DM + tx4;
        *(float4*)(go + g) = make_float4(o[i][0] * inv, o[i][1] * inv,
                                         o[i][2] * inv, o[i][3] * inv);
    }
    if (tx == 0) {
        #pragma unroll
        for (int i = 0; i < 4; i++) {
            int row = bh * SS + qbase + ty4 + i;
            gm[row] = m[i]; gl[row] = l[i];
        }
    }
}

// ---------------------------------------------------------------------------
// Optional: materialize attn = exp(s - m)/l (recompute scores), zero masked.
// ---------------------------------------------------------------------------
__global__ __launch_bounds__(256) void attn_write(
    const float* __restrict__ gq, const float* __restrict__ gk,
    const float* __restrict__ gm, const float* __restrict__ gl,
    float* __restrict__ attn)
{
    __shared__ float Qs[64 * 68];
    __shared__ float Ks[64 * 68];

    const int tid = threadIdx.x;
    const int tx = tid & 15, ty = tid >> 4;
    const int ty4 = ty * 4, tx4 = tx * 4;
    const int qt = 63 - blockIdx.x;
    const int bh = blockIdx.y;
    const int b = bh >> 3, h = bh & 7;
    const int qbase = qt * 64;
    const size_t base = (size_t)b * SS * DM + h * DKH;
    const float scale = 0.125f;
    const size_t arow = (size_t)bh * SS + qbase;

    for (int f = tid; f < 1024; f += 256) {
        int r = f >> 4, c = (f & 15) << 2;
        *(float4*)&Qs[r * 68 + c] =
            *(const float4*)(gq + base + (size_t)(qbase + r) * DM + c);
    }
    float m[4], invl[4];
    #pragma unroll
    for (int i = 0; i < 4; i++) {
        int row = bh * SS + qbase + ty4 + i;
        m[i] = gm[row]; invl[i] = 1.f / gl[row];
    }

    for (int kt = 0; kt < 64; kt++) {
        const int kbase = kt * 64;
        if (kt <= qt) {
            __syncthreads();
            for (int f = tid; f < 1024; f += 256) {
                int r = f >> 4, c = (f & 15) << 2;
                *(float4*)&Ks[r * 68 + c] =
                    *(const float4*)(gk + base + (size_t)(kbase + r) * DM + c);
            }
            __syncthreads();

            float s[4][4] = {};
            dot64(Qs, Ks, ty4, tx4, s);
            const bool diag = (kt == qt);
            #pragma unroll
            for (int i = 0; i < 4; i++) {
                float p[4];
                #pragma unroll
                for (int j = 0; j < 4; j++) {
                    bool masked = diag && (tx4 + j) > (ty4 + i);
                    p[j] = masked ? 0.f : __expf(s[i][j] * scale - m[i]) * invl[i];
                }
                *(float4*)(attn + (arow + ty4 + i) * (size_t)SS + kbase + tx4) =
                    make_float4(p[0], p[1], p[2], p[3]);
            }
        } else {
            float4 z = make_float4(0.f, 0.f, 0.f, 0.f);
            for (int f = tid; f < 1024; f += 256) {
                int r = f >> 4, c = (f & 15) << 2;
                *(float4*)(attn + (arow + r) * (size_t)SS + kbase + c) = z;
            }
        }
    }
}

// ---------------------------------------------------------------------------
extern "C" void kernel_launch(void* const* d_in, const int* in_sizes, int n_in,
                              void* d_out, int out_size)
{
    const float* Q  = (const float*)d_in[0];
    const float* Kx = (const float*)d_in[1];
    const float* V  = (const float*)d_in[2];
    const float* Wq = (const float*)d_in[3];
    const float* bq = (const float*)d_in[4];
    const float* Wk = (const float*)d_in[5];
    const float* bk = (const float*)d_in[6];
    const float* Wv = (const float*)d_in[7];
    const float* bv = (const float*)d_in[8];
    const float* Wo = (const float*)d_in[9];
    const float* bo = (const float*)d_in[10];
    float* out = (float*)d_out;

    float *pq, *pk, *pv, *po, *pm, *pl;
    cudaGetSymbolAddress((void**)&pq, g_q);
    cudaGetSymbolAddress((void**)&pk, g_k);
    cudaGetSymbolAddress((void**)&pv, g_v);
    cudaGetSymbolAddress((void**)&po, g_o);
    cudaGetSymbolAddress((void**)&pm, g_m);
    cudaGetSymbolAddress((void**)&pl, g_l);

    dim3 gg(DM / 64, NROW / 64);   // (8, 128)
    sgemm_bias<<<gg, 256>>>(Q,  Wq, bq, pq, NROW, DM, DM);
    sgemm_bias<<<gg, 256>>>(Kx, Wk, bk, pk, NROW, DM, DM);
    sgemm_bias<<<gg, 256>>>(V,  Wv, bv, pv, NROW, DM, DM);

    const int flash_smem = 4 * 64 * 68 * 4;   // 69632 B
    cudaFuncSetAttribute(flash_attn, cudaFuncAttributeMaxDynamicSharedMemorySize,
                         flash_smem);
    flash_attn<<<dim3(64, 16), 256, flash_smem>>>(pq, pk, pv, po, pm, pl);

    const long long OUTN = (long long)NROW * DM;                       // 4194304
    const long long ATTN = (long long)BB * HH * SS * (long long)SS;    // 268435456
    float* out_ptr = out;
    float* attn_ptr = nullptr;
    if ((long long)out_size == ATTN) {          // harness wants attn only
        attn_ptr = out; out_ptr = nullptr;
    } else if ((long long)out_size >= OUTN + ATTN) {  // out then attn
        attn_ptr = out + OUTN;
    }

    if (out_ptr)
        sgemm_bias<<<gg, 256>>>(po, Wo, bo, out_ptr, NROW, DM, DM);
    if (attn_ptr)
        attn_write<<<dim3(64, 16), 256>>>(pq, pk, pm, pl, attn_ptr);
}

// round 2
// speedup vs baseline: 2.1701x; 2.1701x over previous
#include <cuda_runtime.h>
#include <math.h>
#include <stdint.h>

#define BB 2
#define SS 4096
#define DM 512
#define HH 8
#define DKH 64
#define NROW (BB*SS)   // 8192

// Scratch (allocation-free: __device__ globals)
__device__ float g_q[NROW * DM];
__device__ float g_k[NROW * DM];
__device__ float g_v[NROW * DM];
__device__ float g_o[NROW * DM];
__device__ float g_m[BB * HH * SS];
__device__ float g_l[BB * HH * SS];

__device__ __forceinline__ float tf32r(float f) {
    uint32_t u; asm("cvt.rna.tf32.f32 %0, %1;" : "=r"(u) : "f"(f));
    return __uint_as_float(u);
}
__device__ __forceinline__ uint32_t U(float f) { return __float_as_uint(f); }

// D += A(16x8) * B(8x8), tf32 inputs, fp32 accum
__device__ __forceinline__ void mma8(float4& c,
    uint32_t a0, uint32_t a1, uint32_t a2, uint32_t a3,
    uint32_t b0, uint32_t b1)
{
    asm volatile(
        "mma.sync.aligned.m16n8k8.row.col.f32.tf32.tf32.f32 "
        "{%0,%1,%2,%3},{%4,%5,%6,%7},{%8,%9},{%0,%1,%2,%3};"
        : "+f"(c.x), "+f"(c.y), "+f"(c.z), "+f"(c.w)
        : "r"(a0), "r"(a1), "r"(a2), "r"(a3), "r"(b0), "r"(b1));
}

// ---------------------------------------------------------------------------
// 3xTF32 GEMM: C[M,N] = A[M,K] @ W[N,K]^T + bias[N]
// Block: 256 thr (8 warps), tile 128(M) x 64(N), BK=32. Warp w: rows w*16..+16.
// ---------------------------------------------------------------------------
#define GLDA 36
__global__ __launch_bounds__(256) void gemm_tc(
    const float* __restrict__ A, const float* __restrict__ W,
    const float* __restrict__ bias, float* __restrict__ C,
    int M, int N, int K)
{
    extern __shared__ float smg[];
    float* Ah = smg;                  // 128*36
    float* Al = Ah + 128 * GLDA;
    float* Wh = Al + 128 * GLDA;      // 64*36
    float* Wl = Wh + 64 * GLDA;

    const int tid = threadIdx.x, lane = tid & 31, w = tid >> 5;
    const int r0 = lane >> 2, c4 = lane & 3;
    const int rowBase = blockIdx.y * 128, colBase = blockIdx.x * 64;
    const int m0 = w * 16;

    float4 acc[8];
    #pragma unroll
    for (int i = 0; i < 8; i++) acc[i] = make_float4(0.f, 0.f, 0.f, 0.f);

    for (int k0 = 0; k0 < K; k0 += 32) {
        __syncthreads();
        for (int f = tid; f < 1024; f += 256) {          // A: 128x32
            int r = f >> 3, c = (f & 7) << 2;
            float4 v = *(const float4*)(A + (size_t)(rowBase + r) * K + k0 + c);
            float4 h = make_float4(tf32r(v.x), tf32r(v.y), tf32r(v.z), tf32r(v.w));
            float4 l = make_float4(tf32r(v.x - h.x), tf32r(v.y - h.y),
                                   tf32r(v.z - h.z), tf32r(v.w - h.w));
            *(float4*)&Ah[r * GLDA + c] = h;
            *(float4*)&Al[r * GLDA + c] = l;
        }
        for (int f = tid; f < 512; f += 256) {           // W: 64x32
            int r = f >> 3, c = (f & 7) << 2;
            float4 v = *(const float4*)(W + (size_t)(colBase + r) * K + k0 + c);
            float4 h = make_float4(tf32r(v.x), tf32r(v.y), tf32r(v.z), tf32r(v.w));
            float4 l = make_float4(tf32r(v.x - h.x), tf32r(v.y - h.y),
                                   tf32r(v.z - h.z), tf32r(v.w - h.w));
            *(float4*)&Wh[r * GLDA + c] = h;
            *(float4*)&Wl[r * GLDA + c] = l;
        }
        __syncthreads();

        #pragma unroll
        for (int ks = 0; ks < 4; ks++) {
            int kk = ks * 8;
            uint32_t ah0 = U(Ah[(m0 + r0) * GLDA + kk + c4]);
            uint32_t ah1 = U(Ah[(m0 + r0 + 8) * GLDA + kk + c4]);
            uint32_t ah2 = U(Ah[(m0 + r0) * GLDA + kk + c4 + 4]);
            uint32_t ah3 = U(Ah[(m0 + r0 + 8) * GLDA + kk + c4 + 4]);
            uint32_t al0 = U(Al[(m0 + r0) * GLDA + kk + c4]);
            uint32_t al1 = U(Al[(m0 + r0 + 8) * GLDA + kk + c4]);
            uint32_t al2 = U(Al[(m0 + r0) * GLDA + kk + c4 + 4]);
            uint32_t al3 = U(Al[(m0 + r0 + 8) * GLDA + kk + c4 + 4]);
            #pragma unroll
            for (int nf = 0; nf < 8; nf++) {
                uint32_t bh0 = U(Wh[(nf * 8 + r0) * GLDA + kk + c4]);
                uint32_t bh1 = U(Wh[(nf * 8 + r0) * GLDA + kk + c4 + 4]);
                uint32_t bl0 = U(Wl[(nf * 8 + r0) * GLDA + kk + c4]);
                uint32_t bl1 = U(Wl[(nf * 8 + r0) * GLDA + kk + c4 + 4]);
                mma8(acc[nf], ah0, ah1, ah2, ah3, bh0, bh1);
                mma8(acc[nf], ah0, ah1, ah2, ah3, bl0, bl1);
                mma8(acc[nf], al0, al1, al2, al3, bh0, bh1);
            }
        }
    }

    #pragma unroll
    for (int nf = 0; nf < 8; nf++) {
        int col = colBase + nf * 8 + 2 * c4;
        float bx = bias[col], by = bias[col + 1];
        int r = rowBase + m0 + r0;
        *(float2*)&C[(size_t)r * N + col] =
            make_float2(acc[nf].x + bx, acc[nf].y + by);
        *(float2*)&C[(size_t)(r + 8) * N + col] =
            make_float2(acc[nf].z + bx, acc[nf].w + by);
    }
}

// ---------------------------------------------------------------------------
// Flash attention (causal) with tensor cores. Block: 256 thr (8 warps),
// q-tile = 128 rows (warp w owns rows w*16..+16), key tile = 64.
// QK^T: 3xTF32 (fp32-class). PV: single tf32. Raw scaled scores streamed to
// the attn buffer (finalized by attn_fin). Stores per-row m,l.
// ---------------------------------------------------------------------------
__global__ __launch_bounds__(256) void flash_tc(
    const float* __restrict__ gq, const float* __restrict__ gk,
    const float* __restrict__ gv, float* __restrict__ go,
    float* __restrict__ gm, float* __restrict__ gl,
    float* __restrict__ attn)
{
    extern __shared__ float sm[];
    float* Qh = sm;                   // 128*68
    float* Ql = Qh + 128 * 68;
    float* Kh = Ql + 128 * 68;        // 64*68
    float* Kl = Kh + 64 * 68;
    float* Vs = Kl + 64 * 68;         // 64*68
    float* Ps = Vs + 64 * 68;         // 128*68

    const int tid = threadIdx.x, lane = tid & 31, w = tid >> 5;
    const int r0 = lane >> 2, c4 = lane & 3;
    const int qt = (gridDim.x - 1) - blockIdx.x;    // heavy tiles first
    const int bh = blockIdx.y, b = bh >> 3, h = bh & 7;
    const int qbase = qt * 128;
    const size_t base = (size_t)b * SS * DM + (size_t)h * DKH;
    const int wrow = qbase + w * 16;
    const int mr = w * 16 + r0;          // local q row (first half)
    const int ri0 = wrow + r0, ri1 = ri0 + 8;

    // Load Q tile, pre-scaled by 1/sqrt(dk), split hi/lo
    for (int f = tid; f < 2048; f += 256) {
        int r = f >> 4, c = (f & 15) << 2;
        float4 v = *(const float4*)(gq + base + (size_t)(qbase + r) * DM + c);
        v.x *= 0.125f; v.y *= 0.125f; v.z *= 0.125f; v.w *= 0.125f;
        float4 hh = make_float4(tf32r(v.x), tf32r(v.y), tf32r(v.z), tf32r(v.w));
        float4 ll = make_float4(tf32r(v.x - hh.x), tf32r(v.y - hh.y),
                                tf32r(v.z - hh.z), tf32r(v.w - hh.w));
        *(float4*)&Qh[r * 68 + c] = hh;
        *(float4*)&Ql[r * 68 + c] = ll;
    }

    float4 o[8];
    #pragma unroll
    for (int i = 0; i < 8; i++) o[i] = make_float4(0.f, 0.f, 0.f, 0.f);
    float m0v = -1e30f, m1v = -1e30f, l0v = 0.f, l1v = 0.f;

    const int ktmax = (qbase + 127) >> 6;      // 2*qt+1
    for (int kt = 0; kt <= ktmax; kt++) {
        const int kbase = kt << 6;
        __syncthreads();
        for (int f = tid; f < 1024; f += 256) {
            int r = f >> 4, c = (f & 15) << 2;
            size_t g = base + (size_t)(kbase + r) * DM + c;
            float4 kv = *(const float4*)(gk + g);
            float4 kh = make_float4(tf32r(kv.x), tf32r(kv.y), tf32r(kv.z), tf32r(kv.w));
            float4 kl = make_float4(tf32r(kv.x - kh.x), tf32r(kv.y - kh.y),
                                    tf32r(kv.z - kh.z), tf32r(kv.w - kh.w));
            *(float4*)&Kh[r * 68 + c] = kh;
            *(float4*)&Kl[r * 68 + c] = kl;
            float4 vv = *(const float4*)(gv + g);
            *(float4*)&Vs[r * 68 + c] =
                make_float4(tf32r(vv.x), tf32r(vv.y), tf32r(vv.z), tf32r(vv.w));
        }
        __syncthreads();

        if (kbase <= wrow + 15) {          // tile relevant for this warp
            float4 s[8];
            #pragma unroll
            for (int i = 0; i < 8; i++) s[i] = make_float4(0.f, 0.f, 0.f, 0.f);

            #pragma unroll
            for (int kf = 0; kf < 8; kf++) {
                int kk = kf * 8;
                uint32_t qh0 = U(Qh[mr * 68 + kk + c4]);
                uint32_t qh1 = U(Qh[(mr + 8) * 68 + kk + c4]);
                uint32_t qh2 = U(Qh[mr * 68 + kk + c4 + 4]);
                uint32_t qh3 = U(Qh[(mr + 8) * 68 + kk + c4 + 4]);
                uint32_t ql0 = U(Ql[mr * 68 + kk + c4]);
                uint32_t ql1 = U(Ql[(mr + 8) * 68 + kk + c4]);
                uint32_t ql2 = U(Ql[mr * 68 + kk + c4 + 4]);
                uint32_t ql3 = U(Ql[(mr + 8) * 68 + kk + c4 + 4]);
                #pragma unroll
                for (int nf = 0; nf < 8; nf++) {
                    uint32_t bh0 = U(Kh[(nf * 8 + r0) * 68 + kk + c4]);
                    uint32_t bh1 = U(Kh[(nf * 8 + r0) * 68 + kk + c4 + 4]);
                    uint32_t bl0 = U(Kl[(nf * 8 + r0) * 68 + kk + c4]);
                    uint32_t bl1 = U(Kl[(nf * 8 + r0) * 68 + kk + c4 + 4]);
                    mma8(s[nf], qh0, qh1, qh2, qh3, bh0, bh1);
                    mma8(s[nf], qh0, qh1, qh2, qh3, bl0, bl1);
                    mma8(s[nf], ql0, ql1, ql2, ql3, bh0, bh1);
                }
            }

            if (attn) {    // stream raw scaled scores; finalized later
                #pragma unroll
                for (int nf = 0; nf < 8; nf++) {
                    int col = kbase + nf * 8 + 2 * c4;
                    *(float2*)&attn[((size_t)bh * SS + ri0) * SS + col] =
                        make_float2(s[nf].x, s[nf].y);
                    *(float2*)&attn[((size_t)bh * SS + ri1) * SS + col] =
                        make_float2(s[nf].z, s[nf].w);
                }
            }

            if (kbase + 63 > wrow) {       // causal mask needed
                #pragma unroll
                for (int nf = 0; nf < 8; nf++) {
                    int j0 = kbase + nf * 8 + 2 * c4;
                    if (j0     > ri0) s[nf].x = -INFINITY;
                    if (j0 + 1 > ri0) s[nf].y = -INFINITY;
                    if (j0     > ri1) s[nf].z = -INFINITY;
                    if (j0 + 1 > ri1) s[nf].w = -INFINITY;
                }
            }

            float mt0 = -1e30f, mt1 = -1e30f;
            #pragma unroll
            for (int nf = 0; nf < 8; nf++) {
                mt0 = fmaxf(mt0, fmaxf(s[nf].x, s[nf].y));
                mt1 = fmaxf(mt1, fmaxf(s[nf].z, s[nf].w));
            }
            mt0 = fmaxf(mt0, __shfl_xor_sync(0xffffffffu, mt0, 1));
            mt0 = fmaxf(mt0, __shfl_xor_sync(0xffffffffu, mt0, 2));
            mt1 = fmaxf(mt1, __shfl_xor_sync(0xffffffffu, mt1, 1));
            mt1 = fmaxf(mt1, __shfl_xor_sync(0xffffffffu, mt1, 2));
            float mn0 = fmaxf(m0v, mt0), mn1 = fmaxf(m1v, mt1);
            float al0 = __expf(m0v - mn0), al1 = __expf(m1v - mn1);
            m0v = mn0; m1v = mn1; l0v *= al0; l1v *= al1;

            float rs0 = 0.f, rs1 = 0.f;
            #pragma unroll
            for (int nf = 0; nf < 8; nf++) {
                s[nf].x = __expf(s[nf].x - mn0);
                s[nf].y = __expf(s[nf].y - mn0);
                s[nf].z = __expf(s[nf].z - mn1);
                s[nf].w = __expf(s[nf].w - mn1);
                rs0 += s[nf].x + s[nf].y;
                rs1 += s[nf].z + s[nf].w;
                o[nf].x *= al0; o[nf].y *= al0;
                o[nf].z *= al1; o[nf].w *= al1;
                *(float2*)&Ps[mr * 68 + nf * 8 + 2 * c4] =
                    make_float2(tf32r(s[nf].x), tf32r(s[nf].y));
                *(float2*)&Ps[(mr + 8) * 68 + nf * 8 + 2 * c4] =
                    make_float2(tf32r(s[nf].z), tf32r(s[nf].w));
            }
            rs0 += __shfl_xor_sync(0xffffffffu, rs0, 1);
            rs0 += __shfl_xor_sync(0xffffffffu, rs0, 2);
            rs1 += __shfl_xor_sync(0xffffffffu, rs1, 1);
            rs1 += __shfl_xor_sync(0xffffffffu, rs1, 2);
            l0v += rs0; l1v += rs1;
            __syncwarp();

            // PV: A = Ps (16 x 64 keys), B = Vs (key, d)
            #pragma unroll
            for (int kf = 0; kf < 8; kf++) {
                int kk = kf * 8;
                uint32_t p0 = U(Ps[mr * 68 + kk + c4]);
                uint32_t p1 = U(Ps[(mr + 8) * 68 + kk + c4]);
                uint32_t p2 = U(Ps[mr * 68 + kk + c4 + 4]);
                uint32_t p3 = U(Ps[(mr + 8) * 68 + kk + c4 + 4]);
                #pragma unroll
                for (int nf = 0; nf < 8; nf++) {
                    uint32_t v0 = U(Vs[(kk + c4) * 68 + nf * 8 + r0]);
                    uint32_t v1 = U(Vs[(kk + c4 + 4) * 68 + nf * 8 + r0]);
                    mma8(o[nf], p0, p1, p2, p3, v0, v1);
                }
            }
        }
    }

    float inv0 = 1.f / l0v, inv1 = 1.f / l1v;
    #pragma unroll
    for (int nf = 0; nf < 8; nf++) {
        int col = nf * 8 + 2 * c4;
        *(float2*)(go + base + (size_t)ri0 * DM + col) =
            make_float2(o[nf].x * inv0, o[nf].y * inv0);
        *(float2*)(go + base + (size_t)ri1 * DM + col) =
            make_float2(o[nf].z * inv1, o[nf].w * inv1);
    }
    if (c4 == 0) {
        gm[bh * SS + ri0] = m0v; gm[bh * SS + ri1] = m1v;
        gl[bh * SS + ri0] = l0v; gl[bh * SS + ri1] = l1v;
    }
}

// ---------------------------------------------------------------------------
// Elementwise finalize: attn = exp(s - m)/l in place; zero the masked triangle.
// One float4 per thread.
// ---------------------------------------------------------------------------
__global__ __launch_bounds__(256) void attn_fin(
    float* __restrict__ attn, const float* __restrict__ gm,
    const float* __restrict__ gl)
{
    size_t idx = (size_t)blockIdx.x * 256 + threadIdx.x;
    int j = (int)(idx & (SS / 4 - 1)) << 2;
    size_t r = idx >> 10;                       // bh*SS + i
    int i = (int)(r & (SS - 1));
    float4* p4 = (float4*)attn + idx;
    if (j > i) { *p4 = make_float4(0.f, 0.f, 0.f, 0.f); return; }
    float mi = gm[r];
    float invl = 1.f / gl[r];
    float4 s = *p4;
    float4 p;
    p.x = __expf(s.x - mi) * invl;
    p.y = (j + 1 <= i) ? __expf(s.y - mi) * invl : 0.f;
    p.z = (j + 2 <= i) ? __expf(s.z - mi) * invl : 0.f;
    p.w = (j + 3 <= i) ? __expf(s.w - mi) * invl : 0.f;
    *p4 = p;
}

// ---------------------------------------------------------------------------
extern "C" void kernel_launch(void* const* d_in, const int* in_sizes, int n_in,
                              void* d_out, int out_size)
{
    const float* Q  = (const float*)d_in[0];
    const float* Kx = (const float*)d_in[1];
    const float* V  = (const float*)d_in[2];
    const float* Wq = (const float*)d_in[3];
    const float* bq = (const float*)d_in[4];
    const float* Wk = (const float*)d_in[5];
    const float* bk = (const float*)d_in[6];
    const float* Wv = (const float*)d_in[7];
    const float* bv = (const float*)d_in[8];
    const float* Wo = (const float*)d_in[9];
    const float* bo = (const float*)d_in[10];
    float* out = (float*)d_out;

    float *pq, *pk, *pv, *po, *pm, *pl;
    cudaGetSymbolAddress((void**)&pq, g_q);
    cudaGetSymbolAddress((void**)&pk, g_k);
    cudaGetSymbolAddress((void**)&pv, g_v);
    cudaGetSymbolAddress((void**)&po, g_o);
    cudaGetSymbolAddress((void**)&pm, g_m);
    cudaGetSymbolAddress((void**)&pl, g_l);

    const int GEMM_SMEM  = 384 * GLDA * 4;                    // 55296 B
    const int FLASH_SMEM = (3 * 128 * 68 + 3 * 64 * 68) * 4;  // 156672 B
    cudaFuncSetAttribute(gemm_tc, cudaFuncAttributeMaxDynamicSharedMemorySize,
                         GEMM_SMEM);
    cudaFuncSetAttribute(flash_tc, cudaFuncAttributeMaxDynamicSharedMemorySize,
                         FLASH_SMEM);

    dim3 gp(DM / 64, NROW / 128);     // (8, 64)
    gemm_tc<<<gp, 256, GEMM_SMEM>>>(Q,  Wq, bq, pq, NROW, DM, DM);
    gemm_tc<<<gp, 256, GEMM_SMEM>>>(Kx, Wk, bk, pk, NROW, DM, DM);
    gemm_tc<<<gp, 256, GEMM_SMEM>>>(V,  Wv, bv, pv, NROW, DM, DM);

    const long long OUTN = (long long)NROW * DM;                    // 4194304
    const long long ATTN = (long long)BB * HH * SS * (long long)SS; // 268435456
    float* out_ptr = out;
    float* attn_ptr = nullptr;
    if ((long long)out_size == ATTN) { attn_ptr = out; out_ptr = nullptr; }
    else if ((long long)out_size >= OUTN + ATTN) attn_ptr = out + OUTN;

    flash_tc<<<dim3(SS / 128, 16), 256, FLASH_SMEM>>>(pq, pk, pv, po, pm, pl,
                                                      attn_ptr);

    if (out_ptr)
        gemm_tc<<<gp, 256, GEMM_SMEM>>>(po, Wo, bo, out_ptr, NROW, DM, DM);
    if (attn_ptr)
        attn_fin<<<(unsigned)(ATTN / 4 / 256), 256>>>(attn_ptr, pm, pl);
}

// round 3
// speedup vs baseline: 2.3988x; 1.1054x over previous
#include <cuda_runtime.h>
#include <math.h>
#include <stdint.h>

#define BB 2
#define SS 4096
#define DM 512
#define HH 8
#define DKH 64
#define NROW (BB*SS)   // 8192

__device__ float g_q[NROW * DM];
__device__ float g_k[NROW * DM];
__device__ float g_v[NROW * DM];
__device__ float g_o[NROW * DM];
__device__ float g_m[BB * HH * SS];
__device__ float g_l[BB * HH * SS];

__device__ __forceinline__ float tf32r(float f) {
    uint32_t u; asm("cvt.rna.tf32.f32 %0, %1;" : "=r"(u) : "f"(f));
    return __uint_as_float(u);
}
__device__ __forceinline__ uint32_t U(float f) { return __float_as_uint(f); }

__device__ __forceinline__ void mma8(float4& c,
    uint32_t a0, uint32_t a1, uint32_t a2, uint32_t a3,
    uint32_t b0, uint32_t b1)
{
    asm volatile(
        "mma.sync.aligned.m16n8k8.row.col.f32.tf32.tf32.f32 "
        "{%0,%1,%2,%3},{%4,%5,%6,%7},{%8,%9},{%0,%1,%2,%3};"
        : "+f"(c.x), "+f"(c.y), "+f"(c.z), "+f"(c.w)
        : "r"(a0), "r"(a1), "r"(a2), "r"(a3), "r"(b0), "r"(b1));
}

// Split v0 (cols 8g..8g+3) / v1 (cols 8g+4..8g+7) into hi/lo tf32 planes and
// store 4 packed float4 (h[c], h[c+4], l[c], l[c+4]); sw permutes store order
// so the 4 STS.128 are bank-conflict-free across the quarter-warp.
__device__ __forceinline__ void pack_store(float4* dst, float4 v0, float4 v1, int sw)
{
    float h0[4] = { tf32r(v0.x), tf32r(v0.y), tf32r(v0.z), tf32r(v0.w) };
    float h1[4] = { tf32r(v1.x), tf32r(v1.y), tf32r(v1.z), tf32r(v1.w) };
    float l0[4] = { tf32r(v0.x - h0[0]), tf32r(v0.y - h0[1]),
                    tf32r(v0.z - h0[2]), tf32r(v0.w - h0[3]) };
    float l1[4] = { tf32r(v1.x - h1[0]), tf32r(v1.y - h1[1]),
                    tf32r(v1.z - h1[2]), tf32r(v1.w - h1[3]) };
    #pragma unroll
    for (int jj = 0; jj < 4; jj++) {
        int j = (jj + sw) & 3;
        dst[j] = make_float4(h0[j], h1[j], l0[j], l1[j]);
    }
}

// ---------------------------------------------------------------------------
// 3xTF32 GEMM: C[M,N] = A[M,K] @ W[N,K]^T + bias[N]
// 256 thr, tile 128x64, BK=32, packed fragment smem, register prefetch.
// ---------------------------------------------------------------------------
#define GST 20   // row stride in float4 for packed GEMM tiles
__global__ __launch_bounds__(256, 2) void gemm_tc(
    const float* __restrict__ A, const float* __restrict__ W,
    const float* __restrict__ bias, float* __restrict__ C,
    int M, int N, int K)
{
    extern __shared__ float4 smg4[];
    float4* A4 = smg4;                 // 128 * GST
    float4* W4 = smg4 + 128 * GST;     // 64 * GST

    const int tid = threadIdx.x, lane = tid & 31, w = tid >> 5;
    const int r0 = lane >> 2, c4 = lane & 3;
    const int rowBase = blockIdx.y * 128, colBase = blockIdx.x * 64;
    const int m0 = w * 16;

    float4 acc[8];
    #pragma unroll
    for (int i = 0; i < 8; i++) acc[i] = make_float4(0.f, 0.f, 0.f, 0.f);

    float4 ar[4], wr[2];
    // prefetch k0 = 0
    #pragma unroll
    for (int it = 0; it < 2; it++) {
        int p = tid + it * 256, r = p >> 2, g = p & 3;
        const float* s = A + (size_t)(rowBase + r) * K + g * 8;
        ar[it * 2] = *(const float4*)s; ar[it * 2 + 1] = *(const float4*)(s + 4);
    }
    {
        int r = tid >> 2, g = tid & 3;
        const float* s = W + (size_t)(colBase + r) * K + g * 8;
        wr[0] = *(const float4*)s; wr[1] = *(const float4*)(s + 4);
    }

    for (int k0 = 0; k0 < K; k0 += 32) {
        __syncthreads();
        #pragma unroll
        for (int it = 0; it < 2; it++) {
            int p = tid + it * 256, r = p >> 2, g = p & 3;
            pack_store(&A4[r * GST + g * 4], ar[it * 2], ar[it * 2 + 1],
                       (g >> 1) + 2 * (r & 1));
        }
        {
            int r = tid >> 2, g = tid & 3;
            pack_store(&W4[r * GST + g * 4], wr[0], wr[1],
                       (g >> 1) + 2 * (r & 1));
        }
        __syncthreads();

        if (k0 + 32 < K) {
            #pragma unroll
            for (int it = 0; it < 2; it++) {
                int p = tid + it * 256, r = p >> 2, g = p & 3;
                const float* s = A + (size_t)(rowBase + r) * K + k0 + 32 + g * 8;
                ar[it * 2] = *(const float4*)s; ar[it * 2 + 1] = *(const float4*)(s + 4);
            }
            int r = tid >> 2, g = tid & 3;
            const float* s = W + (size_t)(colBase + r) * K + k0 + 32 + g * 8;
            wr[0] = *(const float4*)s; wr[1] = *(const float4*)(s + 4);
        }

        #pragma unroll
        for (int ks = 0; ks < 4; ks++) {
            float4 aa0 = A4[(m0 + r0) * GST + ks * 4 + c4];
            float4 aa1 = A4[(m0 + r0 + 8) * GST + ks * 4 + c4];
            #pragma unroll
            for (int nf = 0; nf < 8; nf++) {
                float4 wb = W4[(nf * 8 + r0) * GST + ks * 4 + c4];
                mma8(acc[nf], U(aa0.x), U(aa1.x), U(aa0.y), U(aa1.y), U(wb.x), U(wb.y));
                mma8(acc[nf], U(aa0.x), U(aa1.x), U(aa0.y), U(aa1.y), U(wb.z), U(wb.w));
                mma8(acc[nf], U(aa0.z), U(aa1.z), U(aa0.w), U(aa1.w), U(wb.x), U(wb.y));
            }
        }
    }

    #pragma unroll
    for (int nf = 0; nf < 8; nf++) {
        int col = colBase + nf * 8 + 2 * c4;
        float bx = bias[col], by = bias[col + 1];
        int r = rowBase + m0 + r0;
        *(float2*)&C[(size_t)r * N + col] =
            make_float2(acc[nf].x + bx, acc[nf].y + by);
        *(float2*)&C[(size_t)(r + 8) * N + col] =
            make_float2(acc[nf].z + bx, acc[nf].w + by);
    }
}

// ---------------------------------------------------------------------------
// Flash attention (causal), tensor cores, packed fragments + register prefetch.
// q-tile 128 (warp w: rows w*16..+16), key tile 64. QK^T 3xTF32, PV tf32.
// ---------------------------------------------------------------------------
#define FST 36   // row stride in float4 for packed Q/K tiles
__global__ __launch_bounds__(256, 1) void flash_tc(
    const float* __restrict__ gq, const float* __restrict__ gk,
    const float* __restrict__ gv, float* __restrict__ go,
    float* __restrict__ gm, float* __restrict__ gl,
    float* __restrict__ attn)
{
    extern __shared__ float4 sm4[];
    float4* Q4 = sm4;                     // 128 * FST f4
    float4* K4 = sm4 + 128 * FST;         // 64 * FST f4
    float*  Vs = (float*)(sm4 + 128 * FST + 64 * FST);  // 64*68 f32
    float*  Ps = Vs + 64 * 68;                          // 128*68 f32

    const int tid = threadIdx.x, lane = tid & 31, w = tid >> 5;
    const int r0 = lane >> 2, c4 = lane & 3;
    const int qt = (gridDim.x - 1) - blockIdx.x;
    const int bh = blockIdx.y, b = bh >> 3, h = bh & 7;
    const int qbase = qt * 128;
    const size_t base = (size_t)b * SS * DM + (size_t)h * DKH;
    const int wrow = qbase + w * 16;
    const int mr = w * 16 + r0;
    const int ri0 = wrow + r0, ri1 = ri0 + 8;

    // Q tile: pre-scale 1/8, split hi/lo, pack
    #pragma unroll
    for (int it = 0; it < 4; it++) {
        int p = tid + it * 256, r = p >> 3, g = p & 7;
        const float* s = gq + base + (size_t)(qbase + r) * DM + g * 8;
        float4 v0 = *(const float4*)s, v1 = *(const float4*)(s + 4);
        v0.x *= 0.125f; v0.y *= 0.125f; v0.z *= 0.125f; v0.w *= 0.125f;
        v1.x *= 0.125f; v1.y *= 0.125f; v1.z *= 0.125f; v1.w *= 0.125f;
        pack_store(&Q4[r * FST + g * 4], v0, v1, g >> 1);
    }

    float4 o[8];
    #pragma unroll
    for (int i = 0; i < 8; i++) o[i] = make_float4(0.f, 0.f, 0.f, 0.f);
    float m0v = -1e30f, m1v = -1e30f, l0v = 0.f, l1v = 0.f;

    float4 kr[4], vr[4];
    // prefetch tile 0
    #pragma unroll
    for (int it = 0; it < 2; it++) {
        int p = tid + it * 256, r = p >> 3, g = p & 7;
        const float* s = gk + base + (size_t)r * DM + g * 8;
        kr[it * 2] = *(const float4*)s; kr[it * 2 + 1] = *(const float4*)(s + 4);
    }
    #pragma unroll
    for (int it = 0; it < 4; it++) {
        int f = tid + it * 256, r = f >> 4, c = (f & 15) << 2;
        vr[it] = *(const float4*)(gv + base + (size_t)r * DM + c);
    }

    const int ktmax = (qbase + 127) >> 6;
    for (int kt = 0; kt <= ktmax; kt++) {
        const int kbase = kt << 6;
        __syncthreads();
        // store prefetched tile
        #pragma unroll
        for (int it = 0; it < 2; it++) {
            int p = tid + it * 256, r = p >> 3, g = p & 7;
            pack_store(&K4[r * FST + g * 4], kr[it * 2], kr[it * 2 + 1], g >> 1);
        }
        #pragma unroll
        for (int it = 0; it < 4; it++) {
            int f = tid + it * 256, r = f >> 4, c = (f & 15) << 2;
            *(float4*)&Vs[r * 68 + c] = make_float4(
                tf32r(vr[it].x), tf32r(vr[it].y), tf32r(vr[it].z), tf32r(vr[it].w));
        }
        __syncthreads();

        if (kt < ktmax) {
            const int nb = (kt + 1) << 6;
            #pragma unroll
            for (int it = 0; it < 2; it++) {
                int p = tid + it * 256, r = p >> 3, g = p & 7;
                const float* s = gk + base + (size_t)(nb + r) * DM + g * 8;
                kr[it * 2] = *(const float4*)s; kr[it * 2 + 1] = *(const float4*)(s + 4);
            }
            #pragma unroll
            for (int it = 0; it < 4; it++) {
                int f = tid + it * 256, r = f >> 4, c = (f & 15) << 2;
                vr[it] = *(const float4*)(gv + base + (size_t)(nb + r) * DM + c);
            }
        }

        if (kbase <= wrow + 15) {
            float4 s[8];
            #pragma unroll
            for (int i = 0; i < 8; i++) s[i] = make_float4(0.f, 0.f, 0.f, 0.f);

            #pragma unroll
            for (int kf = 0; kf < 8; kf++) {
                float4 qa0 = Q4[mr * FST + kf * 4 + c4];
                float4 qa1 = Q4[(mr + 8) * FST + kf * 4 + c4];
                #pragma unroll
                for (int nf = 0; nf < 8; nf++) {
                    float4 kb = K4[(nf * 8 + r0) * FST + kf * 4 + c4];
                    mma8(s[nf], U(qa0.x), U(qa1.x), U(qa0.y), U(qa1.y), U(kb.x), U(kb.y));
                    mma8(s[nf], U(qa0.x), U(qa1.x), U(qa0.y), U(qa1.y), U(kb.z), U(kb.w));
                    mma8(s[nf], U(qa0.z), U(qa1.z), U(qa0.w), U(qa1.w), U(kb.x), U(kb.y));
                }
            }

            if (attn) {
                #pragma unroll
                for (int nf = 0; nf < 8; nf++) {
                    int col = kbase + nf * 8 + 2 * c4;
                    *(float2*)&attn[((size_t)bh * SS + ri0) * SS + col] =
                        make_float2(s[nf].x, s[nf].y);
                    *(float2*)&attn[((size_t)bh * SS + ri1) * SS + col] =
                        make_float2(s[nf].z, s[nf].w);
                }
            }

            if (kbase + 63 > wrow) {
                #pragma unroll
                for (int nf = 0; nf < 8; nf++) {
                    int j0 = kbase + nf * 8 + 2 * c4;
                    if (j0     > ri0) s[nf].x = -INFINITY;
                    if (j0 + 1 > ri0) s[nf].y = -INFINITY;
                    if (j0     > ri1) s[nf].z = -INFINITY;
                    if (j0 + 1 > ri1) s[nf].w = -INFINITY;
                }
            }

            float mt0 = -1e30f, mt1 = -1e30f;
            #pragma unroll
            for (int nf = 0; nf < 8; nf++) {
                mt0 = fmaxf(mt0, fmaxf(s[nf].x, s[nf].y));
                mt1 = fmaxf(mt1, fmaxf(s[nf].z, s[nf].w));
            }
            mt0 = fmaxf(mt0, __shfl_xor_sync(0xffffffffu, mt0, 1));
            mt0 = fmaxf(mt0, __shfl_xor_sync(0xffffffffu, mt0, 2));
            mt1 = fmaxf(mt1, __shfl_xor_sync(0xffffffffu, mt1, 1));
            mt1 = fmaxf(mt1, __shfl_xor_sync(0xffffffffu, mt1, 2));
            float mn0 = fmaxf(m0v, mt0), mn1 = fmaxf(m1v, mt1);
            float al0 = __expf(m0v - mn0), al1 = __expf(m1v - mn1);
            m0v = mn0; m1v = mn1; l0v *= al0; l1v *= al1;

            float rs0 = 0.f, rs1 = 0.f;
            #pragma unroll
            for (int nf = 0; nf < 8; nf++) {
                s[nf].x = __expf(s[nf].x - mn0);
                s[nf].y = __expf(s[nf].y - mn0);
                s[nf].z = __expf(s[nf].z - mn1);
                s[nf].w = __expf(s[nf].w - mn1);
                rs0 += s[nf].x + s[nf].y;
                rs1 += s[nf].z + s[nf].w;
                o[nf].x *= al0; o[nf].y *= al0;
                o[nf].z *= al1; o[nf].w *= al1;
                *(float2*)&Ps[mr * 68 + nf * 8 + 2 * c4] =
                    make_float2(tf32r(s[nf].x), tf32r(s[nf].y));
                *(float2*)&Ps[(mr + 8) * 68 + nf * 8 + 2 * c4] =
                    make_float2(tf32r(s[nf].z), tf32r(s[nf].w));
            }
            rs0 += __shfl_xor_sync(0xffffffffu, rs0, 1);
            rs0 += __shfl_xor_sync(0xffffffffu, rs0, 2);
            rs1 += __shfl_xor_sync(0xffffffffu, rs1, 1);
            rs1 += __shfl_xor_sync(0xffffffffu, rs1, 2);
            l0v += rs0; l1v += rs1;
            __syncwarp();

            #pragma unroll
            for (int kf = 0; kf < 8; kf++) {
                int kk = kf * 8;
                uint32_t p0 = U(Ps[mr * 68 + kk + c4]);
                uint32_t p1 = U(Ps[(mr + 8) * 68 + kk + c4]);
                uint32_t p2 = U(Ps[mr * 68 + kk + c4 + 4]);
                uint32_t p3 = U(Ps[(mr + 8) * 68 + kk + c4 + 4]);
                #pragma unroll
                for (int nf = 0; nf < 8; nf++) {
                    uint32_t v0 = U(Vs[(kk + c4) * 68 + nf * 8 + r0]);
                    uint32_t v1 = U(Vs[(kk + c4 + 4) * 68 + nf * 8 + r0]);
                    mma8(o[nf], p0, p1, p2, p3, v0, v1);
                }
            }
        }
    }

    float inv0 = 1.f / l0v, inv1 = 1.f / l1v;
    #pragma unroll
    for (int nf = 0; nf < 8; nf++) {
        int col = nf * 8 + 2 * c4;
        *(float2*)(go + base + (size_t)ri0 * DM + col) =
            make_float2(o[nf].x * inv0, o[nf].y * inv0);
        *(float2*)(go + base + (size_t)ri1 * DM + col) =
            make_float2(o[nf].z * inv1, o[nf].w * inv1);
    }
    if (c4 == 0) {
        gm[bh * SS + ri0] = m0v; gm[bh * SS + ri1] = m1v;
        gl[bh * SS + ri0] = l0v; gl[bh * SS + ri1] = l1v;
    }
}

// ---------------------------------------------------------------------------
// attn = exp(s - m)/l in place; zero masked triangle.
// ---------------------------------------------------------------------------
__global__ __launch_bounds__(256) void attn_fin(
    float* __restrict__ attn, const float* __restrict__ gm,
    const float* __restrict__ gl)
{
    size_t idx = (size_t)blockIdx.x * 256 + threadIdx.x;
    int j = (int)(idx & (SS / 4 - 1)) << 2;
    size_t r = idx >> 10;
    int i = (int)(r & (SS - 1));
    float4* p4 = (float4*)attn + idx;
    if (j > i) { *p4 = make_float4(0.f, 0.f, 0.f, 0.f); return; }
    float mi = gm[r];
    float invl = 1.f / gl[r];
    float4 s = *p4;
    float4 p;
    p.x = __expf(s.x - mi) * invl;
    p.y = (j + 1 <= i) ? __expf(s.y - mi) * invl : 0.f;
    p.z = (j + 2 <= i) ? __expf(s.z - mi) * invl : 0.f;
    p.w = (j + 3 <= i) ? __expf(s.w - mi) * invl : 0.f;
    *p4 = p;
}

// ---------------------------------------------------------------------------
extern "C" void kernel_launch(void* const* d_in, const int* in_sizes, int n_in,
                              void* d_out, int out_size)
{
    const float* Q  = (const float*)d_in[0];
    const float* Kx = (const float*)d_in[1];
    const float* V  = (const float*)d_in[2];
    const float* Wq = (const float*)d_in[3];
    const float* bq = (const float*)d_in[4];
    const float* Wk = (const float*)d_in[5];
    const float* bk = (const float*)d_in[6];
    const float* Wv = (const float*)d_in[7];
    const float* bv = (const float*)d_in[8];
    const float* Wo = (const float*)d_in[9];
    const float* bo = (const float*)d_in[10];
    float* out = (float*)d_out;

    float *pq, *pk, *pv, *po, *pm, *pl;
    cudaGetSymbolAddress((void**)&pq, g_q);
    cudaGetSymbolAddress((void**)&pk, g_k);
    cudaGetSymbolAddress((void**)&pv, g_v);
    cudaGetSymbolAddress((void**)&po, g_o);
    cudaGetSymbolAddress((void**)&pm, g_m);
    cudaGetSymbolAddress((void**)&pl, g_l);

    const int GEMM_SMEM  = (128 + 64) * GST * 16;                       // 61440
    const int FLASH_SMEM = (128 + 64) * FST * 16 + (64 + 128) * 68 * 4; // 162816
    cudaFuncSetAttribute(gemm_tc, cudaFuncAttributeMaxDynamicSharedMemorySize,
                         GEMM_SMEM);
    cudaFuncSetAttribute(flash_tc, cudaFuncAttributeMaxDynamicSharedMemorySize,
                         FLASH_SMEM);

    dim3 gp(DM / 64, NROW / 128);
    gemm_tc<<<gp, 256, GEMM_SMEM>>>(Q,  Wq, bq, pq, NROW, DM, DM);
    gemm_tc<<<gp, 256, GEMM_SMEM>>>(Kx, Wk, bk, pk, NROW, DM, DM);
    gemm_tc<<<gp, 256, GEMM_SMEM>>>(V,  Wv, bv, pv, NROW, DM, DM);

    const long long OUTN = (long long)NROW * DM;
    const long long ATTN = (long long)BB * HH * SS * (long long)SS;
    float* out_ptr = out;
    float* attn_ptr = nullptr;
    if ((long long)out_size == ATTN) { attn_ptr = out; out_ptr = nullptr; }
    else if ((long long)out_size >= OUTN + ATTN) attn_ptr = out + OUTN;

    flash_tc<<<dim3(SS / 128, 16), 256, FLASH_SMEM>>>(pq, pk, pv, po, pm, pl,
                                                      attn_ptr);

    if (out_ptr)
        gemm_tc<<<gp, 256, GEMM_SMEM>>>(po, Wo, bo, out_ptr, NROW, DM, DM);
    if (attn_ptr)
        attn_fin<<<(unsigned)(ATTN / 4 / 256), 256>>>(attn_ptr, pm, pl);
}

// round 5
// speedup vs baseline: 3.2344x; 1.3483x over previous
#include <cuda_runtime.h>
#include <math.h>
#include <stdint.h>

#define BB 2
#define SS 4096
#define DM 512
#define HH 8
#define DKH 64
#define NROW (BB*SS)   // 8192

__device__ float g_q[NROW * DM];
__device__ float g_k[NROW * DM];
__device__ float g_v[NROW * DM];
__device__ float g_o[NROW * DM];
__device__ float g_m[BB * HH * SS];
__device__ float g_l[BB * HH * SS];

// lo -> bits[15:0], hi -> bits[31:16]
__device__ __forceinline__ uint32_t bpack(float lo, float hi) {
    uint32_t r;
    asm("cvt.rn.bf16x2.f32 %0, %1, %2;" : "=r"(r) : "f"(hi), "f"(lo));
    return r;
}
// split (x0,x1) pair and (x2,x3) pair into hi/lo bf16 planes
__device__ __forceinline__ uint4 packsplit(float x0, float x1, float x2, float x3) {
    uint4 r;
    r.x = bpack(x0, x1);
    r.y = bpack(x2, x3);
    float h0 = __uint_as_float(r.x << 16);
    float h1 = __uint_as_float(r.x & 0xffff0000u);
    float h2 = __uint_as_float(r.y << 16);
    float h3 = __uint_as_float(r.y & 0xffff0000u);
    r.z = bpack(x0 - h0, x1 - h1);
    r.w = bpack(x2 - h2, x3 - h3);
    return r;
}
__device__ __forceinline__ void psplit(float x, float y, uint32_t& h, uint32_t& l) {
    h = bpack(x, y);
    float hx = __uint_as_float(h << 16);
    float hy = __uint_as_float(h & 0xffff0000u);
    l = bpack(x - hx, y - hy);
}

// D += A(16x16) * B(16x8), bf16 in, fp32 accum
__device__ __forceinline__ void mma16(float4& c,
    uint32_t a0, uint32_t a1, uint32_t a2, uint32_t a3,
    uint32_t b0, uint32_t b1)
{
    asm volatile(
        "mma.sync.aligned.m16n8k16.row.col.f32.bf16.bf16.f32 "
        "{%0,%1,%2,%3},{%4,%5,%6,%7},{%8,%9},{%0,%1,%2,%3};"
        : "+f"(c.x), "+f"(c.y), "+f"(c.z), "+f"(c.w)
        : "r"(a0), "r"(a1), "r"(a2), "r"(a3), "r"(b0), "r"(b1));
}

__device__ __forceinline__ void cp16(uint32_t saddr, const void* gsrc) {
    asm volatile("cp.async.cg.shared.global [%0], [%1], 16;"
                 :: "r"(saddr), "l"(gsrc));
}

// ---------------------------------------------------------------------------
// Split-bf16 GEMM (3-term): C[M,N] = A[M,K] @ W[N,K]^T + bias.
// 256 thr, tile 128x64, BK=32. z selects one of 3 problem slots.
// ---------------------------------------------------------------------------
#define GAST 12   // row stride in uint4 (8 data + 4 pad; 12 % 8 == 4)
__global__ __launch_bounds__(256, 2) void gemm_bf3(
    const float* __restrict__ A0, const float* __restrict__ W0,
    const float* __restrict__ B0, float* __restrict__ C0,
    const float* __restrict__ A1, const float* __restrict__ W1,
    const float* __restrict__ B1, float* __restrict__ C1,
    const float* __restrict__ A2, const float* __restrict__ W2,
    const float* __restrict__ B2, float* __restrict__ C2,
    int M, int N, int K)
{
    extern __shared__ uint4 smg[];
    uint4* Ap = smg;                  // 128 * GAST
    uint4* Wp = smg + 128 * GAST;     // 64 * GAST

    const float* A = A0; const float* W = W0; const float* bias = B0;
    float* C = C0;
    if (blockIdx.z == 1) { A = A1; W = W1; bias = B1; C = C1; }
    else if (blockIdx.z == 2) { A = A2; W = W2; bias = B2; C = C2; }

    const int tid = threadIdx.x, lane = tid & 31, w = tid >> 5;
    const int r0 = lane >> 2, c4 = lane & 3;
    const int rowBase = blockIdx.y * 128, colBase = blockIdx.x * 64;
    const int m0 = w * 16;

    const int arow = tid >> 1, ach = tid & 1;

    float4 acc[8];
    #pragma unroll
    for (int i = 0; i < 8; i++) acc[i] = make_float4(0.f, 0.f, 0.f, 0.f);

    float4 ar[4], wr[4];
    {
        const float* s = A + (size_t)(rowBase + arow) * K + ach * 16;
        #pragma unroll
        for (int i = 0; i < 4; i++) ar[i] = *(const float4*)(s + i * 4);
        if (tid < 128) {
            const float* sw = W + (size_t)(colBase + arow) * K + ach * 16;
            #pragma unroll
            for (int i = 0; i < 4; i++) wr[i] = *(const float4*)(sw + i * 4);
        }
    }

    for (int k0 = 0; k0 < K; k0 += 32) {
        __syncthreads();
        {
            float v[16];
            #pragma unroll
            for (int i = 0; i < 4; i++) ((float4*)v)[i] = ar[i];
            #pragma unroll
            for (int j = 0; j < 4; j++) {
                int cc = (j + arow + 2 * ach) & 3;
                Ap[arow * GAST + ach * 4 + cc] =
                    packsplit(v[2*cc], v[2*cc+1], v[2*cc+8], v[2*cc+9]);
            }
            if (tid < 128) {
                #pragma unroll
                for (int i = 0; i < 4; i++) ((float4*)v)[i] = wr[i];
                #pragma unroll
                for (int j = 0; j < 4; j++) {
                    int cc = (j + arow + 2 * ach) & 3;
                    Wp[arow * GAST + ach * 4 + cc] =
                        packsplit(v[2*cc], v[2*cc+1], v[2*cc+8], v[2*cc+9]);
                }
            }
        }
        __syncthreads();

        if (k0 + 32 < K) {
            const float* s = A + (size_t)(rowBase + arow) * K + k0 + 32 + ach * 16;
            #pragma unroll
            for (int i = 0; i < 4; i++) ar[i] = *(const float4*)(s + i * 4);
            if (tid < 128) {
                const float* sw = W + (size_t)(colBase + arow) * K + k0 + 32 + ach * 16;
                #pragma unroll
                for (int i = 0; i < 4; i++) wr[i] = *(const float4*)(sw + i * 4);
            }
        }

        #pragma unroll
        for (int ch = 0; ch < 2; ch++) {
            uint4 qa = Ap[(m0 + r0) * GAST + ch * 4 + c4];
            uint4 qb = Ap[(m0 + r0 + 8) * GAST + ch * 4 + c4];
            #pragma unroll
            for (int nf = 0; nf < 8; nf++) {
                uint4 wv = Wp[(nf * 8 + r0) * GAST + ch * 4 + c4];
                mma16(acc[nf], qa.x, qb.x, qa.y, qb.y, wv.x, wv.y);
                mma16(acc[nf], qa.x, qb.x, qa.y, qb.y, wv.z, wv.w);
                mma16(acc[nf], qa.z, qb.z, qa.w, qb.w, wv.x, wv.y);
            }
        }
    }

    #pragma unroll
    for (int nf = 0; nf < 8; nf++) {
        int col = colBase + nf * 8 + 2 * c4;
        float bx = bias[col], by = bias[col + 1];
        int r = rowBase + m0 + r0;
        *(float2*)&C[(size_t)r * N + col] =
            make_float2(acc[nf].x + bx, acc[nf].y + by);
        *(float2*)&C[(size_t)(r + 8) * N + col] =
            make_float2(acc[nf].z + bx, acc[nf].w + by);
    }
}

// ---------------------------------------------------------------------------
// Flash attention (causal), split-bf16 tensor cores.
// 256 thr (8 warps), q-tile 128 (warp w: rows w*16..+16), key tile 64.
// QK^T and PV both 3-term split-bf16. P stays in registers (accum==a-frag).
// K staged via cp.async raw buffer + convert; V gathered into registers.
// ---------------------------------------------------------------------------
#define FQT 20   // packed row stride in uint4 (16 data + 4 pad; 20 % 8 == 4)
__global__ __launch_bounds__(256, 2) void flash_bf(
    const float* __restrict__ gq, const float* __restrict__ gk,
    const float* __restrict__ gv, float* __restrict__ go,
    float* __restrict__ gm, float* __restrict__ gl,
    float* __restrict__ attn)
{
    extern __shared__ uint4 sm4[];
    uint4* Qp = sm4;                 // 128 * FQT
    uint4* Kp = sm4 + 128 * FQT;     // 64 * FQT
    uint4* Vp = sm4 + 192 * FQT;     // 64 * FQT
    float* rawK = (float*)(sm4 + 256 * FQT);   // 64 * 68 floats

    const int tid = threadIdx.x, lane = tid & 31, w = tid >> 5;
    const int r0 = lane >> 2, c4 = lane & 3;
    const int qt = (gridDim.x - 1) - blockIdx.x;
    const int bh = blockIdx.y, b = bh >> 3, h = bh & 7;
    const int qbase = qt * 128;
    const size_t base = (size_t)b * SS * DM + (size_t)h * DKH;
    const int wrow = qbase + w * 16;
    const int mr = w * 16 + r0;
    const int ri0 = wrow + r0, ri1 = ri0 + 8;
    const int dcol = tid & 63;                    // V-gather column
    const int vrot = (dcol >> 1) & 3;
    const int rdrot = (r0 >> 1) & 3;              // Vp read rotation

    // ---- issue cp.async for K tile 0
    uint32_t rawK_s = (uint32_t)__cvta_generic_to_shared(rawK);
    #pragma unroll
    for (int i = 0; i < 4; i++) {
        int u = tid + 256 * i, row = u >> 4, seg = u & 15;
        cp16(rawK_s + (row * 68 + seg * 4) * 4,
             gk + base + (size_t)row * DM + seg * 4);
    }
    asm volatile("cp.async.commit_group;");

    // ---- gather V tile 0 into registers
    float4 vr[4];
    #pragma unroll
    for (int i = 0; i < 4; i++) {
        int cc = (tid >> 6) + i * 4, chv = cc >> 2, cv = cc & 3;
        const float* vb = gv + base + (size_t)(chv * 16 + 2 * cv) * DM + dcol;
        vr[i] = make_float4(vb[0], vb[DM], vb[8 * DM], vb[9 * DM]);
    }

    // ---- pack Q (pre-scaled by 1/8)
    #pragma unroll
    for (int i = 0; i < 2; i++) {
        int u = tid + 256 * i, row = u >> 2, ch = u & 3;
        const float* s = gq + base + (size_t)(qbase + row) * DM + ch * 16;
        float v[16];
        #pragma unroll
        for (int j = 0; j < 4; j++) {
            float4 t = *(const float4*)(s + j * 4);
            v[j*4+0] = t.x * 0.125f; v[j*4+1] = t.y * 0.125f;
            v[j*4+2] = t.z * 0.125f; v[j*4+3] = t.w * 0.125f;
        }
        #pragma unroll
        for (int j = 0; j < 4; j++) {
            int cc = (j + ch + 2 * row) & 3;
            Qp[row * FQT + ch * 4 + cc] =
                packsplit(v[2*cc], v[2*cc+1], v[2*cc+8], v[2*cc+9]);
        }
    }

    float4 o[8];
    #pragma unroll
    for (int i = 0; i < 8; i++) o[i] = make_float4(0.f, 0.f, 0.f, 0.f);
    float m0v = -1e30f, m1v = -1e30f, l0v = 0.f, l1v = 0.f;

    const int ktmax = 2 * qt + 1;
    for (int kt = 0; kt <= ktmax; kt++) {
        const int kbase = kt << 6;
        asm volatile("cp.async.wait_group 0;");
        __syncthreads();

        // convert K raw -> packed
        {
            int row = tid >> 2, ch = tid & 3;
            float v[16];
            #pragma unroll
            for (int j = 0; j < 4; j++)
                ((float4*)v)[j] = *(float4*)&rawK[row * 68 + ch * 16 + j * 4];
            #pragma unroll
            for (int j = 0; j < 4; j++) {
                int cc = (j + ch + 2 * row) & 3;
                Kp[row * FQT + ch * 4 + cc] =
                    packsplit(v[2*cc], v[2*cc+1], v[2*cc+8], v[2*cc+9]);
            }
        }
        // store V gather -> packed (d-dependent column rotation)
        #pragma unroll
        for (int i = 0; i < 4; i++) {
            int cc = (tid >> 6) + i * 4, chv = cc >> 2, cv = cc & 3;
            Vp[dcol * FQT + chv * 4 + ((cv + vrot) & 3)] =
                packsplit(vr[i].x, vr[i].y, vr[i].z, vr[i].w);
        }
        __syncthreads();

        if (kt < ktmax) {
            const int nb = (kt + 1) << 6;
            #pragma unroll
            for (int i = 0; i < 4; i++) {
                int u = tid + 256 * i, row = u >> 4, seg = u & 15;
                cp16(rawK_s + (row * 68 + seg * 4) * 4,
                     gk + base + (size_t)(nb + row) * DM + seg * 4);
            }
            asm volatile("cp.async.commit_group;");
            #pragma unroll
            for (int i = 0; i < 4; i++) {
                int cc = (tid >> 6) + i * 4, chv = cc >> 2, cv = cc & 3;
                const float* vb = gv + base +
                    (size_t)(nb + chv * 16 + 2 * cv) * DM + dcol;
                vr[i] = make_float4(vb[0], vb[DM], vb[8 * DM], vb[9 * DM]);
            }
        }

        if (kbase <= wrow + 15) {
            float4 s[8];
            #pragma unroll
            for (int i = 0; i < 8; i++) s[i] = make_float4(0.f, 0.f, 0.f, 0.f);

            // QK^T: 3-term split-bf16
            #pragma unroll
            for (int ch = 0; ch < 4; ch++) {
                uint4 qa = Qp[mr * FQT + ch * 4 + c4];
                uint4 qb = Qp[(mr + 8) * FQT + ch * 4 + c4];
                #pragma unroll
                for (int nf = 0; nf < 8; nf++) {
                    uint4 kv = Kp[(nf * 8 + r0) * FQT + ch * 4 + c4];
                    mma16(s[nf], qa.x, qb.x, qa.y, qb.y, kv.x, kv.y);
                    mma16(s[nf], qa.x, qb.x, qa.y, qb.y, kv.z, kv.w);
                    mma16(s[nf], qa.z, qb.z, qa.w, qb.w, kv.x, kv.y);
                }
            }

            if (attn) {    // raw scaled scores; finalized by attn_fin
                #pragma unroll
                for (int nf = 0; nf < 8; nf++) {
                    int col = kbase + nf * 8 + 2 * c4;
                    *(float2*)&attn[((size_t)bh * SS + ri0) * SS + col] =
                        make_float2(s[nf].x, s[nf].y);
                    *(float2*)&attn[((size_t)bh * SS + ri1) * SS + col] =
                        make_float2(s[nf].z, s[nf].w);
                }
            }

            if (kbase + 63 > wrow) {
                #pragma unroll
                for (int nf = 0; nf < 8; nf++) {
                    int j0 = kbase + nf * 8 + 2 * c4;
                    if (j0     > ri0) s[nf].x = -INFINITY;
                    if (j0 + 1 > ri0) s[nf].y = -INFINITY;
                    if (j0     > ri1) s[nf].z = -INFINITY;
                    if (j0 + 1 > ri1) s[nf].w = -INFINITY;
                }
            }

            float mt0 = -1e30f, mt1 = -1e30f;
            #pragma unroll
            for (int nf = 0; nf < 8; nf++) {
                mt0 = fmaxf(mt0, fmaxf(s[nf].x, s[nf].y));
                mt1 = fmaxf(mt1, fmaxf(s[nf].z, s[nf].w));
            }
            mt0 = fmaxf(mt0, __shfl_xor_sync(0xffffffffu, mt0, 1));
            mt0 = fmaxf(mt0, __shfl_xor_sync(0xffffffffu, mt0, 2));
            mt1 = fmaxf(mt1, __shfl_xor_sync(0xffffffffu, mt1, 1));
            mt1 = fmaxf(mt1, __shfl_xor_sync(0xffffffffu, mt1, 2));
            float mn0 = fmaxf(m0v, mt0), mn1 = fmaxf(m1v, mt1);
            float al0 = __expf(m0v - mn0), al1 = __expf(m1v - mn1);
            m0v = mn0; m1v = mn1; l0v *= al0; l1v *= al1;

            float rs0 = 0.f, rs1 = 0.f;
            #pragma unroll
            for (int nf = 0; nf < 8; nf++) {
                s[nf].x = __expf(s[nf].x - mn0);
                s[nf].y = __expf(s[nf].y - mn0);
                s[nf].z = __expf(s[nf].z - mn1);
                s[nf].w = __expf(s[nf].w - mn1);
                rs0 += s[nf].x + s[nf].y;
                rs1 += s[nf].z + s[nf].w;
                o[nf].x *= al0; o[nf].y *= al0;
                o[nf].z *= al1; o[nf].w *= al1;
            }
            rs0 += __shfl_xor_sync(0xffffffffu, rs0, 1);
            rs0 += __shfl_xor_sync(0xffffffffu, rs0, 2);
            rs1 += __shfl_xor_sync(0xffffffffu, rs1, 1);
            rs1 += __shfl_xor_sync(0xffffffffu, rs1, 2);
            l0v += rs0; l1v += rs1;

            // PV: P a-frags straight from registers (split-bf16, 3-term)
            #pragma unroll
            for (int ch = 0; ch < 4; ch++) {
                int n0 = 2 * ch, n1 = n0 + 1;
                uint32_t a0h, a0l, a1h, a1l, a2h, a2l, a3h, a3l;
                psplit(s[n0].x, s[n0].y, a0h, a0l);
                psplit(s[n0].z, s[n0].w, a1h, a1l);
                psplit(s[n1].x, s[n1].y, a2h, a2l);
                psplit(s[n1].z, s[n1].w, a3h, a3l);
                #pragma unroll
                for (int nf = 0; nf < 8; nf++) {
                    uint4 vv = Vp[(nf * 8 + r0) * FQT + ch * 4 + ((c4 + rdrot) & 3)];
                    mma16(o[nf], a0h, a1h, a2h, a3h, vv.x, vv.y);
                    mma16(o[nf], a0h, a1h, a2h, a3h, vv.z, vv.w);
                    mma16(o[nf], a0l, a1l, a2l, a3l, vv.x, vv.y);
                }
            }
        }
    }

    float inv0 = 1.f / l0v, inv1 = 1.f / l1v;
    #pragma unroll
    for (int nf = 0; nf < 8; nf++) {
        int col = nf * 8 + 2 * c4;
        *(float2*)(go + base + (size_t)ri0 * DM + col) =
            make_float2(o[nf].x * inv0, o[nf].y * inv0);
        *(float2*)(go + base + (size_t)ri1 * DM + col) =
            make_float2(o[nf].z * inv1, o[nf].w * inv1);
    }
    if (c4 == 0) {
        gm[bh * SS + ri0] = m0v; gm[bh * SS + ri1] = m1v;
        gl[bh * SS + ri0] = l0v; gl[bh * SS + ri1] = l1v;
    }
}

// ---------------------------------------------------------------------------
// attn = exp(s - m)/l in place; zero masked triangle.
// ---------------------------------------------------------------------------
__global__ __launch_bounds__(256) void attn_fin(
    float* __restrict__ attn, const float* __restrict__ gm,
    const float* __restrict__ gl)
{
    size_t idx = (size_t)blockIdx.x * 256 + threadIdx.x;
    int j = (int)(idx & (SS / 4 - 1)) << 2;
    size_t r = idx >> 10;
    int i = (int)(r & (SS - 1));
    float4* p4 = (float4*)attn + idx;
    if (j > i) { *p4 = make_float4(0.f, 0.f, 0.f, 0.f); return; }
    float mi = gm[r];
    float invl = 1.f / gl[r];
    float4 s = *p4;
    float4 p;
    p.x = __expf(s.x - mi) * invl;
    p.y = (j + 1 <= i) ? __expf(s.y - mi) * invl : 0.f;
    p.z = (j + 2 <= i) ? __expf(s.z - mi) * invl : 0.f;
    p.w = (j + 3 <= i) ? __expf(s.w - mi) * invl : 0.f;
    *p4 = p;
}

// ---------------------------------------------------------------------------
extern "C" void kernel_launch(void* const* d_in, const int* in_sizes, int n_in,
                              void* d_out, int out_size)
{
    const float* Q  = (const float*)d_in[0];
    const float* Kx = (const float*)d_in[1];
    const float* V  = (const float*)d_in[2];
    const float* Wq = (const float*)d_in[3];
    const float* bq = (const float*)d_in[4];
    const float* Wk = (const float*)d_in[5];
    const float* bk = (const float*)d_in[6];
    const float* Wv = (const float*)d_in[7];
    const float* bv = (const float*)d_in[8];
    const float* Wo = (const float*)d_in[9];
    const float* bo = (const float*)d_in[10];
    float* out = (float*)d_out;

    float *pq, *pk, *pv, *po, *pm, *pl;
    cudaGetSymbolAddress((void**)&pq, g_q);
    cudaGetSymbolAddress((void**)&pk, g_k);
    cudaGetSymbolAddress((void**)&pv, g_v);
    cudaGetSymbolAddress((void**)&po, g_o);
    cudaGetSymbolAddress((void**)&pm, g_m);
    cudaGetSymbolAddress((void**)&pl, g_l);

    const int GEMM_SMEM  = 192 * GAST * 16;              // 36864 B
    const int FLASH_SMEM = 256 * FQT * 16 + 64 * 68 * 4; // 99328 B
    cudaFuncSetAttribute(gemm_bf3, cudaFuncAttributeMaxDynamicSharedMemorySize,
                         GEMM_SMEM);
    cudaFuncSetAttribute(flash_bf, cudaFuncAttributeMaxDynamicSharedMemorySize,
                         FLASH_SMEM);

    // fused Q/K/V projections (z picks slot)
    gemm_bf3<<<dim3(DM / 64, NROW / 128, 3), 256, GEMM_SMEM>>>(
        Q, Wq, bq, pq,  Kx, Wk, bk, pk,  V, Wv, bv, pv, NROW, DM, DM);

    const long long OUTN = (long long)NROW * DM;
    const long long ATTN = (long long)BB * HH * SS * (long long)SS;
    float* out_ptr = out;
    float* attn_ptr = nullptr;
    if ((long long)out_size == ATTN) { attn_ptr = out; out_ptr = nullptr; }
    else if ((long long)out_size >= OUTN + ATTN) attn_ptr = out + OUTN;

    flash_bf<<<dim3(SS / 128, 16), 256, FLASH_SMEM>>>(pq, pk, pv, po, pm, pl,
                                                      attn_ptr);

    if (out_ptr)
        gemm_bf3<<<dim3(DM / 64, NROW / 128, 1), 256, GEMM_SMEM>>>(
            po, Wo, bo, out_ptr,  po, Wo, bo, out_ptr,  po, Wo, bo, out_ptr,
            NROW, DM, DM);
    if (attn_ptr)
        attn_fin<<<(unsigned)(ATTN / 4 / 256), 256>>>(attn_ptr, pm, pl);
}

// round 6
// speedup vs baseline: 3.3189x; 1.0261x over previous
#include <cuda_runtime.h>
#include <math.h>
#include <stdint.h>

#define BB 2
#define SS 4096
#define DM 512
#define HH 8
#define DKH 64
#define NROW (BB*SS)   // 8192

__device__ float g_q[NROW * DM];
__device__ float g_k[NROW * DM];
__device__ float g_v[NROW * DM];
__device__ float g_o[NROW * DM];
__device__ float g_m[BB * HH * SS];
__device__ float g_l[BB * HH * SS];

// lo -> bits[15:0], hi -> bits[31:16]
__device__ __forceinline__ uint32_t bpack(float lo, float hi) {
    uint32_t r;
    asm("cvt.rn.bf16x2.f32 %0, %1, %2;" : "=r"(r) : "f"(hi), "f"(lo));
    return r;
}
__device__ __forceinline__ uint4 packsplit(float x0, float x1, float x2, float x3) {
    uint4 r;
    r.x = bpack(x0, x1);
    r.y = bpack(x2, x3);
    float h0 = __uint_as_float(r.x << 16);
    float h1 = __uint_as_float(r.x & 0xffff0000u);
    float h2 = __uint_as_float(r.y << 16);
    float h3 = __uint_as_float(r.y & 0xffff0000u);
    r.z = bpack(x0 - h0, x1 - h1);
    r.w = bpack(x2 - h2, x3 - h3);
    return r;
}
__device__ __forceinline__ void psplit(float x, float y, uint32_t& h, uint32_t& l) {
    h = bpack(x, y);
    float hx = __uint_as_float(h << 16);
    float hy = __uint_as_float(h & 0xffff0000u);
    l = bpack(x - hx, y - hy);
}

__device__ __forceinline__ void mma16(float4& c,
    uint32_t a0, uint32_t a1, uint32_t a2, uint32_t a3,
    uint32_t b0, uint32_t b1)
{
    asm volatile(
        "mma.sync.aligned.m16n8k16.row.col.f32.bf16.bf16.f32 "
        "{%0,%1,%2,%3},{%4,%5,%6,%7},{%8,%9},{%0,%1,%2,%3};"
        : "+f"(c.x), "+f"(c.y), "+f"(c.z), "+f"(c.w)
        : "r"(a0), "r"(a1), "r"(a2), "r"(a3), "r"(b0), "r"(b1));
}

__device__ __forceinline__ void cp16(uint32_t saddr, const void* gsrc) {
    asm volatile("cp.async.cg.shared.global [%0], [%1], 16;"
                 :: "r"(saddr), "l"(gsrc));
}

// ---------------------------------------------------------------------------
// Split-bf16 GEMM device body: C[128x64 tile] = A @ W^T + bias.
// ---------------------------------------------------------------------------
#define GAST 12
__device__ __forceinline__ void gemm_dev(
    const float* __restrict__ A, const float* __restrict__ W,
    const float* __restrict__ bias, float* __restrict__ C,
    int rowBase, int colBase)
{
    extern __shared__ uint4 smu[];
    uint4* Ap = smu;                  // 128 * GAST
    uint4* Wp = smu + 128 * GAST;     // 64 * GAST
    const int K = DM, N = DM;

    const int tid = threadIdx.x, lane = tid & 31, w = tid >> 5;
    const int r0 = lane >> 2, c4 = lane & 3;
    const int m0 = w * 16;
    const int arow = tid >> 1, ach = tid & 1;

    float4 acc[8];
    #pragma unroll
    for (int i = 0; i < 8; i++) acc[i] = make_float4(0.f, 0.f, 0.f, 0.f);

    float4 ar[4], wr[4];
    {
        const float* s = A + (size_t)(rowBase + arow) * K + ach * 16;
        #pragma unroll
        for (int i = 0; i < 4; i++) ar[i] = *(const float4*)(s + i * 4);
        if (tid < 128) {
            const float* sw = W + (size_t)(colBase + arow) * K + ach * 16;
            #pragma unroll
            for (int i = 0; i < 4; i++) wr[i] = *(const float4*)(sw + i * 4);
        }
    }

    for (int k0 = 0; k0 < K; k0 += 32) {
        __syncthreads();
        {
            float v[16];
            #pragma unroll
            for (int i = 0; i < 4; i++) ((float4*)v)[i] = ar[i];
            #pragma unroll
            for (int j = 0; j < 4; j++) {
                int cc = (j + arow + 2 * ach) & 3;
                Ap[arow * GAST + ach * 4 + cc] =
                    packsplit(v[2*cc], v[2*cc+1], v[2*cc+8], v[2*cc+9]);
            }
            if (tid < 128) {
                #pragma unroll
                for (int i = 0; i < 4; i++) ((float4*)v)[i] = wr[i];
                #pragma unroll
                for (int j = 0; j < 4; j++) {
                    int cc = (j + arow + 2 * ach) & 3;
                    Wp[arow * GAST + ach * 4 + cc] =
                        packsplit(v[2*cc], v[2*cc+1], v[2*cc+8], v[2*cc+9]);
                }
            }
        }
        __syncthreads();

        if (k0 + 32 < K) {
            const float* s = A + (size_t)(rowBase + arow) * K + k0 + 32 + ach * 16;
            #pragma unroll
            for (int i = 0; i < 4; i++) ar[i] = *(const float4*)(s + i * 4);
            if (tid < 128) {
                const float* sw = W + (size_t)(colBase + arow) * K + k0 + 32 + ach * 16;
                #pragma unroll
                for (int i = 0; i < 4; i++) wr[i] = *(const float4*)(sw + i * 4);
            }
        }

        #pragma unroll
        for (int ch = 0; ch < 2; ch++) {
            uint4 qa = Ap[(m0 + r0) * GAST + ch * 4 + c4];
            uint4 qb = Ap[(m0 + r0 + 8) * GAST + ch * 4 + c4];
            #pragma unroll
            for (int nf = 0; nf < 8; nf++) {
                uint4 wv = Wp[(nf * 8 + r0) * GAST + ch * 4 + c4];
                mma16(acc[nf], qa.x, qb.x, qa.y, qb.y, wv.x, wv.y);
                mma16(acc[nf], qa.x, qb.x, qa.y, qb.y, wv.z, wv.w);
                mma16(acc[nf], qa.z, qb.z, qa.w, qb.w, wv.x, wv.y);
            }
        }
    }

    #pragma unroll
    for (int nf = 0; nf < 8; nf++) {
        int col = colBase + nf * 8 + 2 * c4;
        float bx = bias[col], by = bias[col + 1];
        int r = rowBase + m0 + r0;
        *(float2*)&C[(size_t)r * N + col] =
            make_float2(acc[nf].x + bx, acc[nf].y + by);
        *(float2*)&C[(size_t)(r + 8) * N + col] =
            make_float2(acc[nf].z + bx, acc[nf].w + by);
    }
}

// Fused Q/K/V projections (z selects the slot)
__global__ __launch_bounds__(256, 2) void gemm_bf3(
    const float* __restrict__ A0, const float* __restrict__ W0,
    const float* __restrict__ B0, float* __restrict__ C0,
    const float* __restrict__ A1, const float* __restrict__ W1,
    const float* __restrict__ B1, float* __restrict__ C1,
    const float* __restrict__ A2, const float* __restrict__ W2,
    const float* __restrict__ B2, float* __restrict__ C2)
{
    const float* A = A0; const float* W = W0; const float* bias = B0;
    float* C = C0;
    if (blockIdx.z == 1) { A = A1; W = W1; bias = B1; C = C1; }
    else if (blockIdx.z == 2) { A = A2; W = W2; bias = B2; C = C2; }
    gemm_dev(A, W, bias, C, blockIdx.y * 128, blockIdx.x * 64);
}

// ---------------------------------------------------------------------------
// Flash attention (causal), split-bf16. No score streaming (attn handled by
// the epilogue). Stores per-row m,l for the epilogue.
// ---------------------------------------------------------------------------
#define FQT 20
__global__ __launch_bounds__(256, 2) void flash_bf(
    const float* __restrict__ gq, const float* __restrict__ gk,
    const float* __restrict__ gv, float* __restrict__ go,
    float* __restrict__ gm, float* __restrict__ gl)
{
    extern __shared__ uint4 sm4[];
    uint4* Qp = sm4;                 // 128 * FQT
    uint4* Kp = sm4 + 128 * FQT;     // 64 * FQT
    uint4* Vp = sm4 + 192 * FQT;     // 64 * FQT
    float* rawK = (float*)(sm4 + 256 * FQT);   // 64 * 68 floats

    const int tid = threadIdx.x, lane = tid & 31, w = tid >> 5;
    const int r0 = lane >> 2, c4 = lane & 3;
    const int qt = (gridDim.x - 1) - blockIdx.x;
    const int bh = blockIdx.y, b = bh >> 3, h = bh & 7;
    const int qbase = qt * 128;
    const size_t base = (size_t)b * SS * DM + (size_t)h * DKH;
    const int wrow = qbase + w * 16;
    const int mr = w * 16 + r0;
    const int ri0 = wrow + r0, ri1 = ri0 + 8;
    const int dcol = tid & 63;
    const int vrot = (dcol >> 1) & 3;
    const int rdrot = (r0 >> 1) & 3;

    uint32_t rawK_s = (uint32_t)__cvta_generic_to_shared(rawK);
    #pragma unroll
    for (int i = 0; i < 4; i++) {
        int u = tid + 256 * i, row = u >> 4, seg = u & 15;
        cp16(rawK_s + (row * 68 + seg * 4) * 4,
             gk + base + (size_t)row * DM + seg * 4);
    }
    asm volatile("cp.async.commit_group;");

    float4 vr[4];
    #pragma unroll
    for (int i = 0; i < 4; i++) {
        int cc = (tid >> 6) + i * 4, chv = cc >> 2, cv = cc & 3;
        const float* vb = gv + base + (size_t)(chv * 16 + 2 * cv) * DM + dcol;
        vr[i] = make_float4(vb[0], vb[DM], vb[8 * DM], vb[9 * DM]);
    }

    #pragma unroll
    for (int i = 0; i < 2; i++) {
        int u = tid + 256 * i, row = u >> 2, ch = u & 3;
        const float* s = gq + base + (size_t)(qbase + row) * DM + ch * 16;
        float v[16];
        #pragma unroll
        for (int j = 0; j < 4; j++) {
            float4 t = *(const float4*)(s + j * 4);
            v[j*4+0] = t.x * 0.125f; v[j*4+1] = t.y * 0.125f;
            v[j*4+2] = t.z * 0.125f; v[j*4+3] = t.w * 0.125f;
        }
        #pragma unroll
        for (int j = 0; j < 4; j++) {
            int cc = (j + ch + 2 * row) & 3;
            Qp[row * FQT + ch * 4 + cc] =
                packsplit(v[2*cc], v[2*cc+1], v[2*cc+8], v[2*cc+9]);
        }
    }

    float4 o[8];
    #pragma unroll
    for (int i = 0; i < 8; i++) o[i] = make_float4(0.f, 0.f, 0.f, 0.f);
    float m0v = -1e30f, m1v = -1e30f, l0v = 0.f, l1v = 0.f;

    const int ktmax = 2 * qt + 1;
    for (int kt = 0; kt <= ktmax; kt++) {
        const int kbase = kt << 6;
        asm volatile("cp.async.wait_group 0;");
        __syncthreads();

        {
            int row = tid >> 2, ch = tid & 3;
            float v[16];
            #pragma unroll
            for (int j = 0; j < 4; j++)
                ((float4*)v)[j] = *(float4*)&rawK[row * 68 + ch * 16 + j * 4];
            #pragma unroll
            for (int j = 0; j < 4; j++) {
                int cc = (j + ch + 2 * row) & 3;
                Kp[row * FQT + ch * 4 + cc] =
                    packsplit(v[2*cc], v[2*cc+1], v[2*cc+8], v[2*cc+9]);
            }
        }
        #pragma unroll
        for (int i = 0; i < 4; i++) {
            int cc = (tid >> 6) + i * 4, chv = cc >> 2, cv = cc & 3;
            Vp[dcol * FQT + chv * 4 + ((cv + vrot) & 3)] =
                packsplit(vr[i].x, vr[i].y, vr[i].z, vr[i].w);
        }
        __syncthreads();

        if (kt < ktmax) {
            const int nb = (kt + 1) << 6;
            #pragma unroll
            for (int i = 0; i < 4; i++) {
                int u = tid + 256 * i, row = u >> 4, seg = u & 15;
                cp16(rawK_s + (row * 68 + seg * 4) * 4,
                     gk + base + (size_t)(nb + row) * DM + seg * 4);
            }
            asm volatile("cp.async.commit_group;");
            #pragma unroll
            for (int i = 0; i < 4; i++) {
                int cc = (tid >> 6) + i * 4, chv = cc >> 2, cv = cc & 3;
                const float* vb = gv + base +
                    (size_t)(nb + chv * 16 + 2 * cv) * DM + dcol;
                vr[i] = make_float4(vb[0], vb[DM], vb[8 * DM], vb[9 * DM]);
            }
        }

        if (kbase <= wrow + 15) {
            float4 s[8];
            #pragma unroll
            for (int i = 0; i < 8; i++) s[i] = make_float4(0.f, 0.f, 0.f, 0.f);

            #pragma unroll
            for (int ch = 0; ch < 4; ch++) {
                uint4 qa = Qp[mr * FQT + ch * 4 + c4];
                uint4 qb = Qp[(mr + 8) * FQT + ch * 4 + c4];
                #pragma unroll
                for (int nf = 0; nf < 8; nf++) {
                    uint4 kv = Kp[(nf * 8 + r0) * FQT + ch * 4 + c4];
                    mma16(s[nf], qa.x, qb.x, qa.y, qb.y, kv.x, kv.y);
                    mma16(s[nf], qa.x, qb.x, qa.y, qb.y, kv.z, kv.w);
                    mma16(s[nf], qa.z, qb.z, qa.w, qb.w, kv.x, kv.y);
                }
            }

            if (kbase + 63 > wrow) {
                #pragma unroll
                for (int nf = 0; nf < 8; nf++) {
                    int j0 = kbase + nf * 8 + 2 * c4;
                    if (j0     > ri0) s[nf].x = -INFINITY;
                    if (j0 + 1 > ri0) s[nf].y = -INFINITY;
                    if (j0     > ri1) s[nf].z = -INFINITY;
                    if (j0 + 1 > ri1) s[nf].w = -INFINITY;
                }
            }

            float mt0 = -1e30f, mt1 = -1e30f;
            #pragma unroll
            for (int nf = 0; nf < 8; nf++) {
                mt0 = fmaxf(mt0, fmaxf(s[nf].x, s[nf].y));
                mt1 = fmaxf(mt1, fmaxf(s[nf].z, s[nf].w));
            }
            mt0 = fmaxf(mt0, __shfl_xor_sync(0xffffffffu, mt0, 1));
            mt0 = fmaxf(mt0, __shfl_xor_sync(0xffffffffu, mt0, 2));
            mt1 = fmaxf(mt1, __shfl_xor_sync(0xffffffffu, mt1, 1));
            mt1 = fmaxf(mt1, __shfl_xor_sync(0xffffffffu, mt1, 2));
            float mn0 = fmaxf(m0v, mt0), mn1 = fmaxf(m1v, mt1);
            float al0 = __expf(m0v - mn0), al1 = __expf(m1v - mn1);
            m0v = mn0; m1v = mn1; l0v *= al0; l1v *= al1;

            float rs0 = 0.f, rs1 = 0.f;
            #pragma unroll
            for (int nf = 0; nf < 8; nf++) {
                s[nf].x = __expf(s[nf].x - mn0);
                s[nf].y = __expf(s[nf].y - mn0);
                s[nf].z = __expf(s[nf].z - mn1);
                s[nf].w = __expf(s[nf].w - mn1);
                rs0 += s[nf].x + s[nf].y;
                rs1 += s[nf].z + s[nf].w;
                o[nf].x *= al0; o[nf].y *= al0;
                o[nf].z *= al1; o[nf].w *= al1;
            }
            rs0 += __shfl_xor_sync(0xffffffffu, rs0, 1);
            rs0 += __shfl_xor_sync(0xffffffffu, rs0, 2);
            rs1 += __shfl_xor_sync(0xffffffffu, rs1, 1);
            rs1 += __shfl_xor_sync(0xffffffffu, rs1, 2);
            l0v += rs0; l1v += rs1;

            #pragma unroll
            for (int ch = 0; ch < 4; ch++) {
                int n0 = 2 * ch, n1 = n0 + 1;
                uint32_t a0h, a0l, a1h, a1l, a2h, a2l, a3h, a3l;
                psplit(s[n0].x, s[n0].y, a0h, a0l);
                psplit(s[n0].z, s[n0].w, a1h, a1l);
                psplit(s[n1].x, s[n1].y, a2h, a2l);
                psplit(s[n1].z, s[n1].w, a3h, a3l);
                #pragma unroll
                for (int nf = 0; nf < 8; nf++) {
                    uint4 vv = Vp[(nf * 8 + r0) * FQT + ch * 4 + ((c4 + rdrot) & 3)];
                    mma16(o[nf], a0h, a1h, a2h, a3h, vv.x, vv.y);
                    mma16(o[nf], a0h, a1h, a2h, a3h, vv.z, vv.w);
                    mma16(o[nf], a0l, a1l, a2l, a3l, vv.x, vv.y);
                }
            }
        }
    }

    float inv0 = 1.f / l0v, inv1 = 1.f / l1v;
    #pragma unroll
    for (int nf = 0; nf < 8; nf++) {
        int col = nf * 8 + 2 * c4;
        *(float2*)(go + base + (size_t)ri0 * DM + col) =
            make_float2(o[nf].x * inv0, o[nf].y * inv0);
        *(float2*)(go + base + (size_t)ri1 * DM + col) =
            make_float2(o[nf].z * inv1, o[nf].w * inv1);
    }
    if (c4 == 0) {
        gm[bh * SS + ri0] = m0v; gm[bh * SS + ri1] = m1v;
        gl[bh * SS + ri0] = l0v; gl[bh * SS + ri1] = l1v;
    }
}

// ---------------------------------------------------------------------------
// attn materialization: recompute QK^T (same math as flash) and write
// p = exp(s - m)/l directly, plus the zero upper triangle.
// ---------------------------------------------------------------------------
__device__ __forceinline__ void attn_write_dev(
    const float* __restrict__ gq, const float* __restrict__ gk,
    const float* __restrict__ gm, const float* __restrict__ gl,
    float* __restrict__ attn, int idx)
{
    extern __shared__ uint4 sme[];
    uint4* Qp = sme;                 // 128 * FQT
    uint4* Kp = sme + 128 * FQT;     // 64 * FQT
    float* rawK = (float*)(sme + 192 * FQT);   // 64*68 floats

    const int tid = threadIdx.x, lane = tid & 31, w = tid >> 5;
    const int r0 = lane >> 2, c4 = lane & 3;
    const int qt = 31 - (idx >> 4);            // heavy first
    const int bh = idx & 15, b = bh >> 3, h = bh & 7;
    const int qbase = qt * 128;
    const size_t base = (size_t)b * SS * DM + (size_t)h * DKH;
    const int wrow = qbase + w * 16;
    const int mr = w * 16 + r0;
    const int ri0 = wrow + r0, ri1 = ri0 + 8;
    const size_t arow0 = (size_t)bh * SS + ri0;
    const size_t arow1 = (size_t)bh * SS + ri1;

    uint32_t rawK_s = (uint32_t)__cvta_generic_to_shared(rawK);
    #pragma unroll
    for (int i = 0; i < 4; i++) {
        int u = tid + 256 * i, row = u >> 4, seg = u & 15;
        cp16(rawK_s + (row * 68 + seg * 4) * 4,
             gk + base + (size_t)row * DM + seg * 4);
    }
    asm volatile("cp.async.commit_group;");

    #pragma unroll
    for (int i = 0; i < 2; i++) {
        int u = tid + 256 * i, row = u >> 2, ch = u & 3;
        const float* s = gq + base + (size_t)(qbase + row) * DM + ch * 16;
        float v[16];
        #pragma unroll
        for (int j = 0; j < 4; j++) {
            float4 t = *(const float4*)(s + j * 4);
            v[j*4+0] = t.x * 0.125f; v[j*4+1] = t.y * 0.125f;
            v[j*4+2] = t.z * 0.125f; v[j*4+3] = t.w * 0.125f;
        }
        #pragma unroll
        for (int j = 0; j < 4; j++) {
            int cc = (j + ch + 2 * row) & 3;
            Qp[row * FQT + ch * 4 + cc] =
                packsplit(v[2*cc], v[2*cc+1], v[2*cc+8], v[2*cc+9]);
        }
    }

    const float mi0 = gm[bh * SS + ri0], mi1 = gm[bh * SS + ri1];
    const float il0 = 1.f / gl[bh * SS + ri0], il1 = 1.f / gl[bh * SS + ri1];

    const int ktmax = 2 * qt + 1;
    for (int kt = 0; kt <= ktmax; kt++) {
        const int kbase = kt << 6;
        asm volatile("cp.async.wait_group 0;");
        __syncthreads();
        {
            int row = tid >> 2, ch = tid & 3;
            float v[16];
            #pragma unroll
            for (int j = 0; j < 4; j++)
                ((float4*)v)[j] = *(float4*)&rawK[row * 68 + ch * 16 + j * 4];
            #pragma unroll
            for (int j = 0; j < 4; j++) {
                int cc = (j + ch + 2 * row) & 3;
                Kp[row * FQT + ch * 4 + cc] =
                    packsplit(v[2*cc], v[2*cc+1], v[2*cc+8], v[2*cc+9]);
            }
        }
        __syncthreads();
        if (kt < ktmax) {
            const int nb = (kt + 1) << 6;
            #pragma unroll
            for (int i = 0; i < 4; i++) {
                int u = tid + 256 * i, row = u >> 4, seg = u & 15;
                cp16(rawK_s + (row * 68 + seg * 4) * 4,
                     gk + base + (size_t)(nb + row) * DM + seg * 4);
            }
            asm volatile("cp.async.commit_group;");
        }

        if (kbase <= wrow + 15) {
            float4 s[8];
            #pragma unroll
            for (int i = 0; i < 8; i++) s[i] = make_float4(0.f, 0.f, 0.f, 0.f);
            #pragma unroll
            for (int ch = 0; ch < 4; ch++) {
                uint4 qa = Qp[mr * FQT + ch * 4 + c4];
                uint4 qb = Qp[(mr + 8) * FQT + ch * 4 + c4];
                #pragma unroll
                for (int nf = 0; nf < 8; nf++) {
                    uint4 kv = Kp[(nf * 8 + r0) * FQT + ch * 4 + c4];
                    mma16(s[nf], qa.x, qb.x, qa.y, qb.y, kv.x, kv.y);
                    mma16(s[nf], qa.x, qb.x, qa.y, qb.y, kv.z, kv.w);
                    mma16(s[nf], qa.z, qb.z, qa.w, qb.w, kv.x, kv.y);
                }
            }
            if (kbase + 63 > wrow) {
                #pragma unroll
                for (int nf = 0; nf < 8; nf++) {
                    int j0 = kbase + nf * 8 + 2 * c4;
                    if (j0     > ri0) s[nf].x = -INFINITY;
                    if (j0 + 1 > ri0) s[nf].y = -INFINITY;
                    if (j0     > ri1) s[nf].z = -INFINITY;
                    if (j0 + 1 > ri1) s[nf].w = -INFINITY;
                }
            }
            #pragma unroll
            for (int nf = 0; nf < 8; nf++) {
                float2 p0 = make_float2(__expf(s[nf].x - mi0) * il0,
                                        __expf(s[nf].y - mi0) * il0);
                float2 p1 = make_float2(__expf(s[nf].z - mi1) * il1,
                                        __expf(s[nf].w - mi1) * il1);
                unsigned long long u0 = *(unsigned long long*)&p0;
                unsigned long long u1 = *(unsigned long long*)&p1;
                unsigned long long o0 = __shfl_xor_sync(0xffffffffu, u0, 1);
                unsigned long long o1 = __shfl_xor_sync(0xffffffffu, u1, 1);
                if (!(c4 & 1)) {
                    int col = kbase + nf * 8 + 2 * c4;
                    float4 st0, st1;
                    ((unsigned long long*)&st0)[0] = u0;
                    ((unsigned long long*)&st0)[1] = o0;
                    ((unsigned long long*)&st1)[0] = u1;
                    ((unsigned long long*)&st1)[1] = o1;
                    *(float4*)&attn[arow0 * SS + col] = st0;
                    *(float4*)&attn[arow1 * SS + col] = st1;
                }
            }
        } else {
            if (!(c4 & 1)) {
                float4 z = make_float4(0.f, 0.f, 0.f, 0.f);
                #pragma unroll
                for (int nf = 0; nf < 8; nf++) {
                    int col = kbase + nf * 8 + 2 * c4;
                    *(float4*)&attn[arow0 * SS + col] = z;
                    *(float4*)&attn[arow1 * SS + col] = z;
                }
            }
        }
    }

    // zero upper region: cols [z0, SS) for all 128 rows
    const int z0 = (ktmax + 1) * 64;
    const int cw = (SS - z0) >> 2;
    if (cw > 0) {
        float4 z = make_float4(0.f, 0.f, 0.f, 0.f);
        for (int r = 0; r < 128; r++) {
            float* rowp = attn + ((size_t)bh * SS + qbase + r) * SS + z0;
            for (int c = tid; c < cw; c += 256)
                *(float4*)&rowp[4 * c] = z;
        }
    }
}

// Fused epilogue: attn materialization blocks + output-projection blocks.
__global__ __launch_bounds__(256, 2) void epilogue(
    const float* __restrict__ gq, const float* __restrict__ gk,
    const float* __restrict__ gm, const float* __restrict__ gl,
    float* __restrict__ attn,
    const float* __restrict__ go, const float* __restrict__ Wo,
    const float* __restrict__ bo, float* __restrict__ out,
    int nAttn)
{
    if ((int)blockIdx.x < nAttn) {
        attn_write_dev(gq, gk, gm, gl, attn, blockIdx.x);
    } else {
        int zz = blockIdx.x - nAttn;
        gemm_dev(go, Wo, bo, out, (zz >> 3) * 128, (zz & 7) * 64);
    }
}

// ---------------------------------------------------------------------------
extern "C" void kernel_launch(void* const* d_in, const int* in_sizes, int n_in,
                              void* d_out, int out_size)
{
    const float* Q  = (const float*)d_in[0];
    const float* Kx = (const float*)d_in[1];
    const float* V  = (const float*)d_in[2];
    const float* Wq = (const float*)d_in[3];
    const float* bq = (const float*)d_in[4];
    const float* Wk = (const float*)d_in[5];
    const float* bk = (const float*)d_in[6];
    const float* Wv = (const float*)d_in[7];
    const float* bv = (const float*)d_in[8];
    const float* Wo = (const float*)d_in[9];
    const float* bo = (const float*)d_in[10];
    float* out = (float*)d_out;

    float *pq, *pk, *pv, *po, *pm, *pl;
    cudaGetSymbolAddress((void**)&pq, g_q);
    cudaGetSymbolAddress((void**)&pk, g_k);
    cudaGetSymbolAddress((void**)&pv, g_v);
    cudaGetSymbolAddress((void**)&po, g_o);
    cudaGetSymbolAddress((void**)&pm, g_m);
    cudaGetSymbolAddress((void**)&pl, g_l);

    const int GEMM_SMEM  = 192 * GAST * 16;              // 36864
    const int FLASH_SMEM = 256 * FQT * 16 + 64 * 68 * 4; // 99328
    const int EPI_SMEM   = 192 * FQT * 16 + 64 * 68 * 4; // 78848
    cudaFuncSetAttribute(gemm_bf3, cudaFuncAttributeMaxDynamicSharedMemorySize,
                         GEMM_SMEM);
    cudaFuncSetAttribute(flash_bf, cudaFuncAttributeMaxDynamicSharedMemorySize,
                         FLASH_SMEM);
    cudaFuncSetAttribute(epilogue, cudaFuncAttributeMaxDynamicSharedMemorySize,
                         EPI_SMEM);

    gemm_bf3<<<dim3(DM / 64, NROW / 128, 3), 256, GEMM_SMEM>>>(
        Q, Wq, bq, pq,  Kx, Wk, bk, pk,  V, Wv, bv, pv);

    const long long OUTN = (long long)NROW * DM;
    const long long ATTN = (long long)BB * HH * SS * (long long)SS;
    float* out_ptr = out;
    float* attn_ptr = nullptr;
    if ((long long)out_size == ATTN) { attn_ptr = out; out_ptr = nullptr; }
    else if ((long long)out_size >= OUTN + ATTN) attn_ptr = out + OUTN;

    flash_bf<<<dim3(SS / 128, 16), 256, FLASH_SMEM>>>(pq, pk, pv, po, pm, pl);

    int nAttn = attn_ptr ? 512 : 0;
    int nGemm = out_ptr ? 512 : 0;
    epilogue<<<nAttn + nGemm, 256, EPI_SMEM>>>(
        pq, pk, pm, pl, attn_ptr, po, Wo, bo, out_ptr, nAttn);
}

// round 7
// speedup vs baseline: 4.5954x; 1.3846x over previous
#include <cuda_runtime.h>
#include <math.h>
#include <stdint.h>

#define BB 2
#define SS 4096
#define DM 512
#define HH 8
#define DKH 64
#define NROW (BB*SS)   // 8192

#define FQT 20   // flash smem row stride in uint4 (16 data + 4 pad; mod 8 == 4)
#define GAST 12  // gemm smem row stride in uint4 (8 data + 4 pad; mod 8 == 4)

// ---------------- scratch (allocation-free __device__ globals) -------------
__device__ float g_v[NROW * DM];            // V after projection (fp32)
__device__ float g_m[BB * HH * SS];
__device__ float g_l[BB * HH * SS];
__device__ uint4 g_inp[3ull * NROW * 128];  // packed projection inputs (Q,K,V)
__device__ uint4 g_wp[4ull * 512 * 128];    // packed weights (Wq,Wk,Wv,Wo)
__device__ uint4 g_qp[(size_t)BB * HH * SS * 16];  // packed attention q (scaled)
__device__ uint4 g_kp[(size_t)BB * HH * SS * 16];  // packed attention k
__device__ uint4 g_vt[(size_t)BB * HH * 64 * 1024]; // packed V transposed
__device__ uint4 g_op[(size_t)BB * HH * SS * 16];  // packed attention output

// ---------------- helpers --------------------------------------------------
__device__ __forceinline__ uint32_t bpack(float lo, float hi) {
    uint32_t r;
    asm("cvt.rn.bf16x2.f32 %0, %1, %2;" : "=r"(r) : "f"(hi), "f"(lo));
    return r;
}
__device__ __forceinline__ uint4 packsplit(float x0, float x1, float x2, float x3) {
    uint4 r;
    r.x = bpack(x0, x1);
    r.y = bpack(x2, x3);
    float h0 = __uint_as_float(r.x << 16);
    float h1 = __uint_as_float(r.x & 0xffff0000u);
    float h2 = __uint_as_float(r.y << 16);
    float h3 = __uint_as_float(r.y & 0xffff0000u);
    r.z = bpack(x0 - h0, x1 - h1);
    r.w = bpack(x2 - h2, x3 - h3);
    return r;
}
__device__ __forceinline__ void psplit(float x, float y, uint32_t& h, uint32_t& l) {
    h = bpack(x, y);
    float hx = __uint_as_float(h << 16);
    float hy = __uint_as_float(h & 0xffff0000u);
    l = bpack(x - hx, y - hy);
}
__device__ __forceinline__ void mma16(float4& c,
    uint32_t a0, uint32_t a1, uint32_t a2, uint32_t a3,
    uint32_t b0, uint32_t b1)
{
    asm volatile(
        "mma.sync.aligned.m16n8k16.row.col.f32.bf16.bf16.f32 "
        "{%0,%1,%2,%3},{%4,%5,%6,%7},{%8,%9},{%0,%1,%2,%3};"
        : "+f"(c.x), "+f"(c.y), "+f"(c.z), "+f"(c.w)
        : "r"(a0), "r"(a1), "r"(a2), "r"(a3), "r"(b0), "r"(b1));
}
__device__ __forceinline__ void cp16(uint32_t saddr, const void* gsrc) {
    asm volatile("cp.async.cg.shared.global [%0], [%1], 16;"
                 :: "r"(saddr), "l"(gsrc));
}

// ---------------------------------------------------------------------------
// packmat: fp32 [rows x 512] -> packed split-bf16 [rows x 32ch x 4cc] uint4
// ---------------------------------------------------------------------------
__global__ __launch_bounds__(256) void packmat(
    const float* __restrict__ src, uint4* __restrict__ dst, int total)
{
    int t = blockIdx.x * 256 + threadIdx.x;
    if (t >= total) return;
    const float* s = src + (size_t)t * 16;
    uint4* d = dst + (size_t)t * 4;
    float v[16];
    #pragma unroll
    for (int j = 0; j < 4; j++) ((float4*)v)[j] = *(const float4*)(s + j * 4);
    #pragma unroll
    for (int cc = 0; cc < 4; cc++)
        d[cc] = packsplit(v[2*cc], v[2*cc+1], v[2*cc+8], v[2*cc+9]);
}

// ---------------------------------------------------------------------------
// vtrans: g_v fp32 -> packed transposed per (b,h): [d][kch][cc], cc packs
// tokens (2cc, 2cc+1, 2cc+8, 2cc+9) within a 16-token group.
// ---------------------------------------------------------------------------
__global__ __launch_bounds__(256) void vtrans()
{
    __shared__ float sv[64 * 68];
    int bh = blockIdx.y, tile = blockIdx.x;
    int b = bh >> 3, h = bh & 7;
    const float* src = g_v + (size_t)b * SS * DM + (size_t)h * DKH
                           + (size_t)tile * 64 * DM;
    int tid = threadIdx.x;
    #pragma unroll
    for (int i = 0; i < 4; i++) {
        int f = tid + i * 256, r = f >> 4, c = (f & 15) << 2;
        *(float4*)&sv[r * 68 + c] = *(const float4*)(src + (size_t)r * DM + c);
    }
    __syncthreads();
    int d = tid & 63, g = tid >> 6;
    uint4* dst = g_vt + (((size_t)(bh * 64 + d)) << 10) + (size_t)(tile * 4 + g) * 4;
    #pragma unroll
    for (int cc = 0; cc < 4; cc++) {
        int t0 = 16 * g + 2 * cc;
        dst[cc] = packsplit(sv[t0 * 68 + d], sv[(t0 + 1) * 68 + d],
                            sv[(t0 + 8) * 68 + d], sv[(t0 + 9) * 68 + d]);
    }
}

// ---------------------------------------------------------------------------
// GEMM core (packed in, double-buffered cp.async): 128x64 tile, BK=32.
// amode 0: A plain packed rows [row*128 + kch*4 + cc]
// amode 1: A head-interleaved packed (g_op layout)
// output: fp32 (Cf) or packed attention layout (Cp, with oscale)
// ---------------------------------------------------------------------------
__device__ __forceinline__ void gemm_issue(
    const uint4* __restrict__ Ag, int amode, const uint4* __restrict__ Wg,
    uint32_t smA, uint32_t smW, int rowBase, int colBase, int k0, int tid)
{
    #pragma unroll
    for (int i = 0; i < 4; i++) {
        int u = tid + i * 256, row = u >> 3, q8 = u & 7;
        int grow = rowBase + row;
        size_t src;
        if (amode == 0) {
            src = (size_t)grow * 128 + (size_t)((k0 >> 4) * 4 + q8);
        } else {
            int b = grow >> 12, s = grow & (SS - 1);
            int h = k0 >> 6, ch0 = (k0 & 63) >> 4;
            src = ((size_t)(b * HH + h) * SS + s) * 16 + ch0 * 4 + q8;
        }
        cp16(smA + (row * GAST + q8) * 16, Ag + src);
    }
    #pragma unroll
    for (int i = 0; i < 2; i++) {
        int u = tid + i * 256, row = u >> 3, q8 = u & 7;
        size_t src = (size_t)(colBase + row) * 128 + (size_t)((k0 >> 4) * 4 + q8);
        cp16(smW + (row * GAST + q8) * 16, Wg + src);
    }
    asm volatile("cp.async.commit_group;");
}

__device__ __forceinline__ void gemm_core(
    const uint4* __restrict__ Ag, int amode, const uint4* __restrict__ Wg,
    const float* __restrict__ bias,
    float* __restrict__ Cf, uint4* __restrict__ Cp, float oscale,
    int rowBase, int colBase)
{
    extern __shared__ uint4 smu[];
    const int HB = 192 * GAST;    // one buffer: A(128*GAST) + W(64*GAST)
    uint32_t smb = (uint32_t)__cvta_generic_to_shared(smu);
    const uint4* aP[2] = { smu, smu + HB };
    const uint4* wP[2] = { smu + 128 * GAST, smu + HB + 128 * GAST };
    uint32_t aA[2] = { smb, smb + (uint32_t)HB * 16 };
    uint32_t wA[2] = { smb + 128 * GAST * 16, smb + (uint32_t)HB * 16 + 128 * GAST * 16 };

    const int tid = threadIdx.x, lane = tid & 31, w = tid >> 5;
    const int r0 = lane >> 2, c4 = lane & 3;
    const int m0 = w * 16;

    float4 acc[8];
    #pragma unroll
    for (int i = 0; i < 8; i++) acc[i] = make_float4(0.f, 0.f, 0.f, 0.f);

    gemm_issue(Ag, amode, Wg, aA[0], wA[0], rowBase, colBase, 0, tid);
    int buf = 0;
    for (int k0 = 0; k0 < DM; k0 += 32) {
        asm volatile("cp.async.wait_group 0;");
        __syncthreads();
        if (k0 + 32 < DM)
            gemm_issue(Ag, amode, Wg, aA[buf ^ 1], wA[buf ^ 1],
                       rowBase, colBase, k0 + 32, tid);
        const uint4* Ap = aP[buf];
        const uint4* Wp = wP[buf];
        #pragma unroll
        for (int ch = 0; ch < 2; ch++) {
            uint4 aa = Ap[(m0 + r0) * GAST + ch * 4 + c4];
            uint4 ab = Ap[(m0 + r0 + 8) * GAST + ch * 4 + c4];
            #pragma unroll
            for (int nf = 0; nf < 8; nf++) {
                uint4 wv = Wp[(nf * 8 + r0) * GAST + ch * 4 + c4];
                mma16(acc[nf], aa.x, ab.x, aa.y, ab.y, wv.x, wv.y);
                mma16(acc[nf], aa.x, ab.x, aa.y, ab.y, wv.z, wv.w);
                mma16(acc[nf], aa.z, ab.z, aa.w, ab.w, wv.x, wv.y);
            }
        }
        buf ^= 1;
    }

    int r = rowBase + m0 + r0;
    if (Cp) {
        int h = colBase >> 6;
        int b = r >> 12, s = r & (SS - 1);
        size_t ro0 = ((size_t)(b * HH + h) * SS + s) * 16;
        size_t ro1 = ro0 + 8 * 16;
        #pragma unroll
        for (int ch = 0; ch < 4; ch++) {
            int col = colBase + ch * 16 + 2 * c4;
            float b0 = bias[col],     b1 = bias[col + 1];
            float b8 = bias[col + 8], b9 = bias[col + 9];
            Cp[ro0 + ch * 4 + c4] = packsplit(
                (acc[2*ch].x + b0) * oscale, (acc[2*ch].y + b1) * oscale,
                (acc[2*ch+1].x + b8) * oscale, (acc[2*ch+1].y + b9) * oscale);
            Cp[ro1 + ch * 4 + c4] = packsplit(
                (acc[2*ch].z + b0) * oscale, (acc[2*ch].w + b1) * oscale,
                (acc[2*ch+1].z + b8) * oscale, (acc[2*ch+1].w + b9) * oscale);
        }
    } else {
        #pragma unroll
        for (int nf = 0; nf < 8; nf++) {
            int col = colBase + nf * 8 + 2 * c4;
            float bx = bias[col], by = bias[col + 1];
            *(float2*)&Cf[(size_t)r * DM + col] =
                make_float2(acc[nf].x + bx, acc[nf].y + by);
            *(float2*)&Cf[(size_t)(r + 8) * DM + col] =
                make_float2(acc[nf].z + bx, acc[nf].w + by);
        }
    }
}

// Projections: z=0 Q->packed(x0.125), z=1 K->packed, z=2 V->fp32
__global__ __launch_bounds__(256, 2) void gemm_proj(
    const float* __restrict__ bq, const float* __restrict__ bk,
    const float* __restrict__ bv)
{
    int z = blockIdx.z;
    const uint4* Ag = g_inp + (size_t)z * NROW * 128;
    const uint4* Wg = g_wp + (size_t)z * 512 * 128;
    int rb = blockIdx.y * 128, cb = blockIdx.x * 64;
    if (z == 0)      gemm_core(Ag, 0, Wg, bq, nullptr, g_qp, 0.125f, rb, cb);
    else if (z == 1) gemm_core(Ag, 0, Wg, bk, nullptr, g_kp, 1.f, rb, cb);
    else             gemm_core(Ag, 0, Wg, bv, g_v, nullptr, 1.f, rb, cb);
}

// ---------------------------------------------------------------------------
// Flash attention (causal): packed in, Q fragments in registers,
// K+V double-buffered cp.async, packed output.
// ---------------------------------------------------------------------------
__device__ __forceinline__ void kv_issue(uint32_t smK, uint32_t smV,
                                         int bh, int kbase, int tid)
{
    #pragma unroll
    for (int i = 0; i < 4; i++) {
        int u = tid + i * 256, row = u >> 4, q = u & 15;
        cp16(smK + (row * FQT + q) * 16,
             g_kp + ((size_t)bh * SS + kbase + row) * 16 + q);
    }
    #pragma unroll
    for (int i = 0; i < 4; i++) {
        int u = tid + i * 256, d = u >> 4, q = u & 15;
        cp16(smV + (d * FQT + q) * 16,
             g_vt + (((size_t)(bh * 64 + d)) << 10) + (kbase >> 4) * 4 + q);
    }
    asm volatile("cp.async.commit_group;");
}

__global__ __launch_bounds__(256, 2) void flash_bf()
{
    extern __shared__ uint4 smf[];
    const int KB = 64 * FQT;
    uint32_t smb = (uint32_t)__cvta_generic_to_shared(smf);
    const uint4* Kb[2] = { smf, smf + 2 * KB };
    const uint4* Vb[2] = { smf + KB, smf + 3 * KB };
    uint32_t Ka[2] = { smb, smb + (uint32_t)(2 * KB) * 16 };
    uint32_t Va[2] = { smb + (uint32_t)KB * 16, smb + (uint32_t)(3 * KB) * 16 };

    const int tid = threadIdx.x, lane = tid & 31, w = tid >> 5;
    const int r0 = lane >> 2, c4 = lane & 3;
    const int qt = 31 - blockIdx.x;
    const int bh = blockIdx.y;
    const int qbase = qt * 128;
    const int wrow = qbase + w * 16;
    const int ri0 = wrow + r0, ri1 = ri0 + 8;

    kv_issue(Ka[0], Va[0], bh, 0, tid);

    uint4 qa[4], qb[4];
    {
        size_t q0 = ((size_t)bh * SS + ri0) * 16;
        size_t q1 = ((size_t)bh * SS + ri1) * 16;
        #pragma unroll
        for (int ch = 0; ch < 4; ch++) {
            qa[ch] = g_qp[q0 + ch * 4 + c4];
            qb[ch] = g_qp[q1 + ch * 4 + c4];
        }
    }

    float4 o[8];
    #pragma unroll
    for (int i = 0; i < 8; i++) o[i] = make_float4(0.f, 0.f, 0.f, 0.f);
    float m0v = -1e30f, m1v = -1e30f, l0v = 0.f, l1v = 0.f;

    int buf = 0;
    const int ktmax = 2 * qt + 1;
    for (int kt = 0; kt <= ktmax; kt++) {
        const int kbase = kt << 6;
        asm volatile("cp.async.wait_group 0;");
        __syncthreads();
        if (kt < ktmax) kv_issue(Ka[buf ^ 1], Va[buf ^ 1], bh, (kt + 1) << 6, tid);

        if (kbase <= wrow + 15) {
            const uint4* Kp = Kb[buf];
            const uint4* Vp = Vb[buf];
            float4 s[8];
            #pragma unroll
            for (int i = 0; i < 8; i++) s[i] = make_float4(0.f, 0.f, 0.f, 0.f);

            #pragma unroll
            for (int ch = 0; ch < 4; ch++) {
                #pragma unroll
                for (int nf = 0; nf < 8; nf++) {
                    uint4 kv = Kp[(nf * 8 + r0) * FQT + ch * 4 + c4];
                    mma16(s[nf], qa[ch].x, qb[ch].x, qa[ch].y, qb[ch].y, kv.x, kv.y);
                    mma16(s[nf], qa[ch].x, qb[ch].x, qa[ch].y, qb[ch].y, kv.z, kv.w);
                    mma16(s[nf], qa[ch].z, qb[ch].z, qa[ch].w, qb[ch].w, kv.x, kv.y);
                }
            }

            if (kbase + 63 > wrow) {
                #pragma unroll
                for (int nf = 0; nf < 8; nf++) {
                    int j0 = kbase + nf * 8 + 2 * c4;
                    if (j0     > ri0) s[nf].x = -INFINITY;
                    if (j0 + 1 > ri0) s[nf].y = -INFINITY;
                    if (j0     > ri1) s[nf].z = -INFINITY;
                    if (j0 + 1 > ri1) s[nf].w = -INFINITY;
                }
            }

            float mt0 = -1e30f, mt1 = -1e30f;
            #pragma unroll
            for (int nf = 0; nf < 8; nf++) {
                mt0 = fmaxf(mt0, fmaxf(s[nf].x, s[nf].y));
                mt1 = fmaxf(mt1, fmaxf(s[nf].z, s[nf].w));
            }
            mt0 = fmaxf(mt0, __shfl_xor_sync(0xffffffffu, mt0, 1));
            mt0 = fmaxf(mt0, __shfl_xor_sync(0xffffffffu, mt0, 2));
            mt1 = fmaxf(mt1, __shfl_xor_sync(0xffffffffu, mt1, 1));
            mt1 = fmaxf(mt1, __shfl_xor_sync(0xffffffffu, mt1, 2));
            float mn0 = fmaxf(m0v, mt0), mn1 = fmaxf(m1v, mt1);
            float al0 = __expf(m0v - mn0), al1 = __expf(m1v - mn1);
            m0v = mn0; m1v = mn1; l0v *= al0; l1v *= al1;

            float rs0 = 0.f, rs1 = 0.f;
            #pragma unroll
            for (int nf = 0; nf < 8; nf++) {
                s[nf].x = __expf(s[nf].x - mn0);
                s[nf].y = __expf(s[nf].y - mn0);
                s[nf].z = __expf(s[nf].z - mn1);
                s[nf].w = __expf(s[nf].w - mn1);
                rs0 += s[nf].x + s[nf].y;
                rs1 += s[nf].z + s[nf].w;
                o[nf].x *= al0; o[nf].y *= al0;
                o[nf].z *= al1; o[nf].w *= al1;
            }
            rs0 += __shfl_xor_sync(0xffffffffu, rs0, 1);
            rs0 += __shfl_xor_sync(0xffffffffu, rs0, 2);
            rs1 += __shfl_xor_sync(0xffffffffu, rs1, 1);
            rs1 += __shfl_xor_sync(0xffffffffu, rs1, 2);
            l0v += rs0; l1v += rs1;

            #pragma unroll
            for (int ch = 0; ch < 4; ch++) {
                int n0 = 2 * ch, n1 = n0 + 1;
                uint32_t a0h, a0l, a1h, a1l, a2h, a2l, a3h, a3l;
                psplit(s[n0].x, s[n0].y, a0h, a0l);
                psplit(s[n0].z, s[n0].w, a1h, a1l);
                psplit(s[n1].x, s[n1].y, a2h, a2l);
                psplit(s[n1].z, s[n1].w, a3h, a3l);
                #pragma unroll
                for (int nf = 0; nf < 8; nf++) {
                    uint4 vv = Vp[(nf * 8 + r0) * FQT + ch * 4 + c4];
                    mma16(o[nf], a0h, a1h, a2h, a3h, vv.x, vv.y);
                    mma16(o[nf], a0h, a1h, a2h, a3h, vv.z, vv.w);
                    mma16(o[nf], a0l, a1l, a2l, a3l, vv.x, vv.y);
                }
            }
        }
        buf ^= 1;
    }

    float inv0 = 1.f / l0v, inv1 = 1.f / l1v;
    size_t ro0 = ((size_t)bh * SS + ri0) * 16;
    size_t ro1 = ((size_t)bh * SS + ri1) * 16;
    #pragma unroll
    for (int ch = 0; ch < 4; ch++) {
        g_op[ro0 + ch * 4 + c4] = packsplit(
            o[2*ch].x * inv0, o[2*ch].y * inv0,
            o[2*ch+1].x * inv0, o[2*ch+1].y * inv0);
        g_op[ro1 + ch * 4 + c4] = packsplit(
            o[2*ch].z * inv1, o[2*ch].w * inv1,
            o[2*ch+1].z * inv1, o[2*ch+1].w * inv1);
    }
    if (c4 == 0) {
        g_m[bh * SS + ri0] = m0v; g_m[bh * SS + ri1] = m1v;
        g_l[bh * SS + ri0] = l0v; g_l[bh * SS + ri1] = l1v;
    }
}

// ---------------------------------------------------------------------------
// attn materialization (recompute QK^T from packed q,k; double-buffered K)
// ---------------------------------------------------------------------------
__device__ __forceinline__ void k_issue(uint32_t smK, int bh, int kbase, int tid)
{
    #pragma unroll
    for (int i = 0; i < 4; i++) {
        int u = tid + i * 256, row = u >> 4, q = u & 15;
        cp16(smK + (row * FQT + q) * 16,
             g_kp + ((size_t)bh * SS + kbase + row) * 16 + q);
    }
    asm volatile("cp.async.commit_group;");
}

__device__ __forceinline__ void attn_write_dev(float* __restrict__ attn, int idx)
{
    extern __shared__ uint4 sme[];
    const int KB = 64 * FQT;
    uint32_t smb = (uint32_t)__cvta_generic_to_shared(sme);
    const uint4* Kb[2] = { sme, sme + KB };
    uint32_t Ka[2] = { smb, smb + (uint32_t)KB * 16 };

    const int tid = threadIdx.x, lane = tid & 31, w = tid >> 5;
    const int r0 = lane >> 2, c4 = lane & 3;
    const int qt = 31 - (idx >> 4);
    const int bh = idx & 15;
    const int qbase = qt * 128;
    const int wrow = qbase + w * 16;
    const int ri0 = wrow + r0, ri1 = ri0 + 8;
    const size_t arow0 = (size_t)bh * SS + ri0;
    const size_t arow1 = (size_t)bh * SS + ri1;

    k_issue(Ka[0], bh, 0, tid);

    uint4 qa[4], qb[4];
    {
        size_t q0 = ((size_t)bh * SS + ri0) * 16;
        size_t q1 = ((size_t)bh * SS + ri1) * 16;
        #pragma unroll
        for (int ch = 0; ch < 4; ch++) {
            qa[ch] = g_qp[q0 + ch * 4 + c4];
            qb[ch] = g_qp[q1 + ch * 4 + c4];
        }
    }

    const float mi0 = g_m[bh * SS + ri0], mi1 = g_m[bh * SS + ri1];
    const float il0 = 1.f / g_l[bh * SS + ri0], il1 = 1.f / g_l[bh * SS + ri1];

    int buf = 0;
    const int ktmax = 2 * qt + 1;
    for (int kt = 0; kt <= ktmax; kt++) {
        const int kbase = kt << 6;
        asm volatile("cp.async.wait_group 0;");
        __syncthreads();
        if (kt < ktmax) k_issue(Ka[buf ^ 1], bh, (kt + 1) << 6, tid);

        if (kbase <= wrow + 15) {
            const uint4* Kp = Kb[buf];
            float4 s[8];
            #pragma unroll
            for (int i = 0; i < 8; i++) s[i] = make_float4(0.f, 0.f, 0.f, 0.f);
            #pragma unroll
            for (int ch = 0; ch < 4; ch++) {
                #pragma unroll
                for (int nf = 0; nf < 8; nf++) {
                    uint4 kv = Kp[(nf * 8 + r0) * FQT + ch * 4 + c4];
                    mma16(s[nf], qa[ch].x, qb[ch].x, qa[ch].y, qb[ch].y, kv.x, kv.y);
                    mma16(s[nf], qa[ch].x, qb[ch].x, qa[ch].y, qb[ch].y, kv.z, kv.w);
                    mma16(s[nf], qa[ch].z, qb[ch].z, qa[ch].w, qb[ch].w, kv.x, kv.y);
                }
            }
            if (kbase + 63 > wrow) {
                #pragma unroll
                for (int nf = 0; nf < 8; nf++) {
                    int j0 = kbase + nf * 8 + 2 * c4;
                    if (j0     > ri0) s[nf].x = -INFINITY;
                    if (j0 + 1 > ri0) s[nf].y = -INFINITY;
                    if (j0     > ri1) s[nf].z = -INFINITY;
                    if (j0 + 1 > ri1) s[nf].w = -INFINITY;
                }
            }
            #pragma unroll
            for (int nf = 0; nf < 8; nf++) {
                float2 p0 = make_float2(__expf(s[nf].x - mi0) * il0,
                                        __expf(s[nf].y - mi0) * il0);
                float2 p1 = make_float2(__expf(s[nf].z - mi1) * il1,
                                        __expf(s[nf].w - mi1) * il1);
                unsigned long long u0 = *(unsigned long long*)&p0;
                unsigned long long u1 = *(unsigned long long*)&p1;
                unsigned long long o0 = __shfl_xor_sync(0xffffffffu, u0, 1);
                unsigned long long o1 = __shfl_xor_sync(0xffffffffu, u1, 1);
                if (!(c4 & 1)) {
                    int col = kbase + nf * 8 + 2 * c4;
                    float4 st0, st1;
                    ((unsigned long long*)&st0)[0] = u0;
                    ((unsigned long long*)&st0)[1] = o0;
                    ((unsigned long long*)&st1)[0] = u1;
                    ((unsigned long long*)&st1)[1] = o1;
                    *(float4*)&attn[arow0 * SS + col] = st0;
                    *(float4*)&attn[arow1 * SS + col] = st1;
                }
            }
        } else {
            if (!(c4 & 1)) {
                float4 z = make_float4(0.f, 0.f, 0.f, 0.f);
                #pragma unroll
                for (int nf = 0; nf < 8; nf++) {
                    int col = kbase + nf * 8 + 2 * c4;
                    *(float4*)&attn[arow0 * SS + col] = z;
                    *(float4*)&attn[arow1 * SS + col] = z;
                }
            }
        }
        buf ^= 1;
    }

    const int z0 = (ktmax + 1) * 64;
    const int cw = (SS - z0) >> 2;
    if (cw > 0) {
        float4 z = make_float4(0.f, 0.f, 0.f, 0.f);
        for (int r = 0; r < 128; r++) {
            float* rowp = attn + ((size_t)bh * SS + qbase + r) * SS + z0;
            for (int c = tid; c < cw; c += 256)
                *(float4*)&rowp[4 * c] = z;
        }
    }
}

// Fused epilogue: attn materialization blocks + output-projection blocks.
__global__ __launch_bounds__(256, 2) void epilogue(
    float* __restrict__ attn, const float* __restrict__ bo,
    float* __restrict__ out, int nAttn)
{
    if ((int)blockIdx.x < nAttn) {
        attn_write_dev(attn, blockIdx.x);
    } else {
        int zz = blockIdx.x - nAttn;
        gemm_core(g_op, 1, g_wp + 3ull * 512 * 128, bo, out, nullptr, 1.f,
                  (zz >> 3) * 128, (zz & 7) * 64);
    }
}

// ---------------------------------------------------------------------------
extern "C" void kernel_launch(void* const* d_in, const int* in_sizes, int n_in,
                              void* d_out, int out_size)
{
    const float* Q  = (const float*)d_in[0];
    const float* Kx = (const float*)d_in[1];
    const float* V  = (const float*)d_in[2];
    const float* Wq = (const float*)d_in[3];
    const float* bq = (const float*)d_in[4];
    const float* Wk = (const float*)d_in[5];
    const float* bk = (const float*)d_in[6];
    const float* Wv = (const float*)d_in[7];
    const float* bv = (const float*)d_in[8];
    const float* Wo = (const float*)d_in[9];
    const float* bo = (const float*)d_in[10];
    float* out = (float*)d_out;

    uint4 *pinp, *pwp;
    cudaGetSymbolAddress((void**)&pinp, g_inp);
    cudaGetSymbolAddress((void**)&pwp, g_wp);

    const int GEMM_SMEM  = 2 * 192 * GAST * 16;   // 73728
    const int FLASH_SMEM = 4 * 64 * FQT * 16;     // 81920
    const int EPI_SMEM   = 2 * 192 * GAST * 16;   // 73728
    cudaFuncSetAttribute(gemm_proj, cudaFuncAttributeMaxDynamicSharedMemorySize,
                         GEMM_SMEM);
    cudaFuncSetAttribute(flash_bf, cudaFuncAttributeMaxDynamicSharedMemorySize,
                         FLASH_SMEM);
    cudaFuncSetAttribute(epilogue, cudaFuncAttributeMaxDynamicSharedMemorySize,
                         EPI_SMEM);

    // pack inputs + weights
    packmat<<<NROW * 32 / 256, 256>>>(Q,  pinp + 0ull * NROW * 128, NROW * 32);
    packmat<<<NROW * 32 / 256, 256>>>(Kx, pinp + 1ull * NROW * 128, NROW * 32);
    packmat<<<NROW * 32 / 256, 256>>>(V,  pinp + 2ull * NROW * 128, NROW * 32);
    packmat<<<512 * 32 / 256, 256>>>(Wq, pwp + 0ull * 512 * 128, 512 * 32);
    packmat<<<512 * 32 / 256, 256>>>(Wk, pwp + 1ull * 512 * 128, 512 * 32);
    packmat<<<512 * 32 / 256, 256>>>(Wv, pwp + 2ull * 512 * 128, 512 * 32);
    packmat<<<512 * 32 / 256, 256>>>(Wo, pwp + 3ull * 512 * 128, 512 * 32);

    gemm_proj<<<dim3(DM / 64, NROW / 128, 3), 256, GEMM_SMEM>>>(bq, bk, bv);
    vtrans<<<dim3(SS / 64, 16), 256>>>();

    const long long OUTN = (long long)NROW * DM;
    const long long ATTN = (long long)BB * HH * SS * (long long)SS;
    float* out_ptr = out;
    float* attn_ptr = nullptr;
    if ((long long)out_size == ATTN) { attn_ptr = out; out_ptr = nullptr; }
    else if ((long long)out_size >= OUTN + ATTN) attn_ptr = out + OUTN;

    flash_bf<<<dim3(SS / 128, 16), 256, FLASH_SMEM>>>();

    int nAttn = attn_ptr ? 512 : 0;
    int nGemm = out_ptr ? 512 : 0;
    epilogue<<<nAttn + nGemm, 256, EPI_SMEM>>>(attn_ptr, bo, out_ptr, nAttn);
}